// round 1
// baseline (speedup 1.0000x reference)
#include <cuda_runtime.h>

#define SEQ 2048
#define DIM 1024
#define NH 16
#define HDIM 64
#define SCALE 0.125f
#define ENTW 0.5f
#define DECAYC 0.1f
#define SUPW 0.3f
#define LNEPS 1e-5f
#define PI_F 3.14159265358979323846f

// ---------------- scratch (static device allocations are the sanctioned path) ----
__device__ float g_q[SEQ * DIM];
__device__ float g_k[SEQ * DIM];
__device__ float g_v[SEQ * DIM];
__device__ float g_eq[SEQ * DIM];
__device__ float g_ek[SEQ * DIM];
__device__ float g_mx[SEQ * DIM];   // mixed values
__device__ float g_ctx[SEQ * DIM];  // attention output (pre-Wo)
__device__ float g_res[SEQ * DIM];  // residual (pre-LN)
__device__ float g_ca[SEQ * NH];    // SUP * amp * cos(phase)
__device__ float g_sa[SEQ * NH];    // SUP * amp * sin(phase)

// ---------------- generic 128x128x16 fp32 tiled GEMM:  C = A @ W^T + bias (+resid)
// A: [M,1024] row-major, W: [N,1024] row-major, C: [M,1024] (we always have N,K=1024)
__device__ __forceinline__ void gemm128(const float* __restrict__ A,
                                        const float* __restrict__ W,
                                        const float* __restrict__ bias,
                                        const float* __restrict__ resid,
                                        float* __restrict__ C) {
    __shared__ __align__(16) float As[16][132];
    __shared__ __align__(16) float Bs[16][132];
    const int K = 1024;
    int m0 = blockIdx.y * 128;
    int n0 = blockIdx.x * 128;
    int tid = threadIdx.x;
    int tm = tid >> 4;   // 0..15
    int tn = tid & 15;   // 0..15

    float acc[8][8];
#pragma unroll
    for (int i = 0; i < 8; i++)
#pragma unroll
        for (int j = 0; j < 8; j++) acc[i][j] = 0.f;

    for (int k0 = 0; k0 < K; k0 += 16) {
#pragma unroll
        for (int t = 0; t < 2; t++) {
            int f = tid + (t << 8);       // 0..511
            int row = f >> 2;             // 0..127
            int kc = (f & 3) << 2;        // 0,4,8,12
            float4 a = *(const float4*)(A + (size_t)(m0 + row) * K + k0 + kc);
            As[kc + 0][row] = a.x; As[kc + 1][row] = a.y;
            As[kc + 2][row] = a.z; As[kc + 3][row] = a.w;
            float4 w = *(const float4*)(W + (size_t)(n0 + row) * K + k0 + kc);
            Bs[kc + 0][row] = w.x; Bs[kc + 1][row] = w.y;
            Bs[kc + 2][row] = w.z; Bs[kc + 3][row] = w.w;
        }
        __syncthreads();
#pragma unroll
        for (int kk = 0; kk < 16; kk++) {
            float a[8], b[8];
            *(float4*)(a)     = *(const float4*)&As[kk][tm * 8];
            *(float4*)(a + 4) = *(const float4*)&As[kk][tm * 8 + 4];
            *(float4*)(b)     = *(const float4*)&Bs[kk][tn * 8];
            *(float4*)(b + 4) = *(const float4*)&Bs[kk][tn * 8 + 4];
#pragma unroll
            for (int i = 0; i < 8; i++)
#pragma unroll
                for (int j = 0; j < 8; j++) acc[i][j] += a[i] * b[j];
        }
        __syncthreads();
    }

#pragma unroll
    for (int i = 0; i < 8; i++) {
        int row = m0 + tm * 8 + i;
#pragma unroll
        for (int jj = 0; jj < 8; jj += 4) {
            int col = n0 + tn * 8 + jj;
            float4 o;
            o.x = acc[i][jj + 0] + bias[col + 0];
            o.y = acc[i][jj + 1] + bias[col + 1];
            o.z = acc[i][jj + 2] + bias[col + 2];
            o.w = acc[i][jj + 3] + bias[col + 3];
            if (resid) {
                const float4 r = *(const float4*)(resid + (size_t)row * DIM + col);
                o.x += r.x; o.y += r.y; o.z += r.z; o.w += r.w;
            }
            *(float4*)(C + (size_t)row * DIM + col) = o;
        }
    }
}

// ---------------- K1: fused 5-way projection GEMM (Q,K,V,EQ,EK) ------------------
__global__ __launch_bounds__(256) void k_gemm5(
    const float* __restrict__ hs,
    const float* __restrict__ Wq, const float* __restrict__ bq,
    const float* __restrict__ Wk, const float* __restrict__ bk,
    const float* __restrict__ Wv, const float* __restrict__ bv,
    const float* __restrict__ Weq, const float* __restrict__ beq,
    const float* __restrict__ Wek, const float* __restrict__ bek) {
    const float* W; const float* b; float* C;
    switch (blockIdx.z) {
        case 0:  W = Wq;  b = bq;  C = g_q;  break;
        case 1:  W = Wk;  b = bk;  C = g_k;  break;
        case 2:  W = Wv;  b = bv;  C = g_v;  break;
        case 3:  W = Weq; b = beq; C = g_eq; break;
        default: W = Wek; b = bek; C = g_ek; break;
    }
    gemm128(hs, W, b, nullptr, C);
}

// ---------------- K5: output projection + residual -------------------------------
__global__ __launch_bounds__(256) void k_gemmo(const float* __restrict__ hs,
                                               const float* __restrict__ Wo,
                                               const float* __restrict__ bo) {
    gemm128(g_ctx, Wo, bo, hs, g_res);
}

// ---------------- K2: amplitudes & phases -> ca/sa --------------------------------
__global__ __launch_bounds__(256) void k_ampph(const float* __restrict__ hs,
                                               const float* __restrict__ aw,
                                               const float* __restrict__ ab,
                                               const float* __restrict__ pw,
                                               const float* __restrict__ pb) {
    __shared__ float row[DIM];
    __shared__ float acc[32];
    int s = blockIdx.x, tid = threadIdx.x;
    for (int i = tid; i < DIM; i += 256) row[i] = hs[(size_t)s * DIM + i];
    __syncthreads();
    int w = tid >> 5, lane = tid & 31;
#pragma unroll
    for (int t = 0; t < 4; t++) {
        int o = w * 4 + t;          // 0..31  (0..15 amp, 16..31 phase)
        int hh = o & 15;
        const float* wp = (o < 16) ? (aw + (size_t)hh * DIM) : (pw + (size_t)hh * DIM);
        float sum = 0.f;
        for (int i = lane; i < DIM; i += 32) sum += row[i] * wp[i];
#pragma unroll
        for (int m = 16; m; m >>= 1) sum += __shfl_xor_sync(0xffffffffu, sum, m);
        if (lane == 0) acc[o] = sum + ((o < 16) ? ab[hh] : pb[hh]);
    }
    __syncthreads();
    if (tid < NH) {
        float a = 1.f / (1.f + expf(-acc[tid]));
        float ph = tanhf(acc[16 + tid]) * PI_F;
        float sp, cp;
        sincosf(ph, &sp, &cp);
        g_ca[s * NH + tid] = SUPW * a * cp;
        g_sa[s * NH + tid] = SUPW * a * sp;
    }
}

// ---------------- K3: per-head superposition mixer -> g_mx ------------------------
__global__ __launch_bounds__(256) void k_mixed(const float* __restrict__ mw_g,
                                               const float* __restrict__ mb_g) {
    __shared__ float mw[64][65];
    __shared__ float vt[32][65];
    __shared__ float sp[32][65];
    __shared__ float mb[64];
    int h = blockIdx.y, s0 = blockIdx.x * 32;
    int tid = threadIdx.x;
    for (int i = tid; i < 4096; i += 256) mw[i >> 6][i & 63] = mw_g[h * 4096 + i];
    if (tid < 64) mb[tid] = mb_g[h * 64 + tid];
    for (int i = tid; i < 2048; i += 256)
        vt[i >> 6][i & 63] = g_v[(size_t)(s0 + (i >> 6)) * DIM + h * HDIM + (i & 63)];
    __syncthreads();

    int r = tid >> 3;            // 0..31
    int ob = (tid & 7) * 8;      // 0..56
    float a[8];
#pragma unroll
    for (int j = 0; j < 8; j++) a[j] = 0.f;
    for (int d = 0; d < 64; d++) {
        float vv = vt[r][d];
#pragma unroll
        for (int j = 0; j < 8; j++) a[j] += vv * mw[ob + j][d];
    }
#pragma unroll
    for (int j = 0; j < 8; j++) sp[r][ob + j] = a[j] + mb[ob + j];
    __syncthreads();

    for (int i = tid; i < 2048; i += 256) {
        int rr = i >> 6, o = i & 63;
        float ca = g_ca[(s0 + rr) * NH + h];
        float sa = g_sa[(s0 + rr) * NH + h];
        g_mx[(size_t)(s0 + rr) * DIM + h * HDIM + o] =
            vt[rr][o] + ca * sp[rr][o] + sa * sp[rr][(o + 63) & 63];
    }
}

// ---------------- K4: flash attention with entanglement + decay -------------------
// grid (32 q-tiles, 16 heads), 256 threads.  BM=BN=HD=64.
#define ASTR 68
#define ATTN_SMEM_BYTES ((6 * 64 * ASTR + 128) * 4)

__global__ __launch_bounds__(256, 2) void k_attn() {
    extern __shared__ __align__(16) float sm[];
    float* Qs = sm;
    float* Es = Qs + 64 * ASTR;
    float* Ks = Es + 64 * ASTR;
    float* Fs = Ks + 64 * ASTR;
    float* Ms = Fs + 64 * ASTR;
    float* Ps = Ms + 64 * ASTR;
    float* dtab = Ps + 64 * ASTR;

    int h = blockIdx.y;
    int q0 = blockIdx.x * 64;
    int tid = threadIdx.x;
    int ty = tid >> 4, tx = tid & 15;
    int hoff = h * HDIM;

    // load Q / EQ tiles once
#pragma unroll
    for (int t = 0; t < 4; t++) {
        int f = tid + (t << 8);
        int r = f >> 4, c = (f & 15) << 2;
        *(float4*)&Qs[r * ASTR + c] = *(const float4*)&g_q[(size_t)(q0 + r) * DIM + hoff + c];
        *(float4*)&Es[r * ASTR + c] = *(const float4*)&g_eq[(size_t)(q0 + r) * DIM + hoff + c];
    }

    float m_i[4], l_i[4], O[4][4];
#pragma unroll
    for (int i = 0; i < 4; i++) {
        m_i[i] = -1e30f; l_i[i] = 0.f;
#pragma unroll
        for (int j = 0; j < 4; j++) O[i][j] = 0.f;
    }

    for (int kt = 0; kt < 32; kt++) {
        int k0 = kt * 64;
        int dq = q0 - k0; int adq = dq < 0 ? -dq : dq;
        bool ent = (adq <= 384);   // beyond this decay < 1e-14 -> negligible

        __syncthreads();   // prev-iter PV done; (first iter) Q/EQ ready
#pragma unroll
        for (int t = 0; t < 4; t++) {
            int f = tid + (t << 8);
            int r = f >> 4, c = (f & 15) << 2;
            *(float4*)&Ks[r * ASTR + c] = *(const float4*)&g_k[(size_t)(k0 + r) * DIM + hoff + c];
            *(float4*)&Ms[r * ASTR + c] = *(const float4*)&g_mx[(size_t)(k0 + r) * DIM + hoff + c];
            if (ent)
                *(float4*)&Fs[r * ASTR + c] = *(const float4*)&g_ek[(size_t)(k0 + r) * DIM + hoff + c];
        }
        if (ent && tid < 127) {
            float dd = (float)(dq + tid - 63);   // (q0-k0) + (r-c)
            dtab[tid] = __expf(-DECAYC * fabsf(dd));
        }
        __syncthreads();

        float acc1[4][4], acc2[4][4];
#pragma unroll
        for (int i = 0; i < 4; i++)
#pragma unroll
            for (int j = 0; j < 4; j++) { acc1[i][j] = 0.f; acc2[i][j] = 0.f; }

        if (ent) {
#pragma unroll
            for (int d = 0; d < 64; d += 4) {
                float4 q[4], e[4];
#pragma unroll
                for (int i = 0; i < 4; i++) {
                    q[i] = *(const float4*)&Qs[(ty * 4 + i) * ASTR + d];
                    e[i] = *(const float4*)&Es[(ty * 4 + i) * ASTR + d];
                }
#pragma unroll
                for (int j = 0; j < 4; j++) {
                    float4 k = *(const float4*)&Ks[(tx + 16 * j) * ASTR + d];
                    float4 f = *(const float4*)&Fs[(tx + 16 * j) * ASTR + d];
#pragma unroll
                    for (int i = 0; i < 4; i++) {
                        acc1[i][j] += q[i].x * k.x + q[i].y * k.y + q[i].z * k.z + q[i].w * k.w;
                        acc2[i][j] += e[i].x * f.x + e[i].y * f.y + e[i].z * f.z + e[i].w * f.w;
                    }
                }
            }
        } else {
#pragma unroll
            for (int d = 0; d < 64; d += 4) {
                float4 q[4];
#pragma unroll
                for (int i = 0; i < 4; i++)
                    q[i] = *(const float4*)&Qs[(ty * 4 + i) * ASTR + d];
#pragma unroll
                for (int j = 0; j < 4; j++) {
                    float4 k = *(const float4*)&Ks[(tx + 16 * j) * ASTR + d];
#pragma unroll
                    for (int i = 0; i < 4; i++)
                        acc1[i][j] += q[i].x * k.x + q[i].y * k.y + q[i].z * k.z + q[i].w * k.w;
                }
            }
        }

        // online softmax over this key tile
#pragma unroll
        for (int i = 0; i < 4; i++) {
            int rr = ty * 4 + i;
            float sv[4];
            float mx = -1e30f;
#pragma unroll
            for (int j = 0; j < 4; j++) {
                int cc = tx + 16 * j;
                float s = SCALE * acc1[i][j];
                if (ent) s += (ENTW * SCALE) * dtab[rr - cc + 63] * acc2[i][j];
                sv[j] = s;
                mx = fmaxf(mx, s);
            }
#pragma unroll
            for (int o = 1; o < 16; o <<= 1)
                mx = fmaxf(mx, __shfl_xor_sync(0xffffffffu, mx, o));
            float mnew = fmaxf(m_i[i], mx);
            float alpha = __expf(m_i[i] - mnew);
            float sum = 0.f;
#pragma unroll
            for (int j = 0; j < 4; j++) {
                float p = __expf(sv[j] - mnew);
                Ps[rr * ASTR + tx + 16 * j] = p;
                sum += p;
            }
#pragma unroll
            for (int o = 1; o < 16; o <<= 1)
                sum += __shfl_xor_sync(0xffffffffu, sum, o);
            l_i[i] = l_i[i] * alpha + sum;
            m_i[i] = mnew;
#pragma unroll
            for (int j = 0; j < 4; j++) O[i][j] *= alpha;
        }
        __syncthreads();

        // O += P @ Mixed   (O columns = tx*4 + j)
#pragma unroll
        for (int c = 0; c < 64; c += 4) {
            float4 pr[4];
#pragma unroll
            for (int i = 0; i < 4; i++)
                pr[i] = *(const float4*)&Ps[(ty * 4 + i) * ASTR + c];
            float4 w0 = *(const float4*)&Ms[(c + 0) * ASTR + tx * 4];
            float4 w1 = *(const float4*)&Ms[(c + 1) * ASTR + tx * 4];
            float4 w2 = *(const float4*)&Ms[(c + 2) * ASTR + tx * 4];
            float4 w3 = *(const float4*)&Ms[(c + 3) * ASTR + tx * 4];
#pragma unroll
            for (int i = 0; i < 4; i++) {
                O[i][0] += pr[i].x * w0.x + pr[i].y * w1.x + pr[i].z * w2.x + pr[i].w * w3.x;
                O[i][1] += pr[i].x * w0.y + pr[i].y * w1.y + pr[i].z * w2.y + pr[i].w * w3.y;
                O[i][2] += pr[i].x * w0.z + pr[i].y * w1.z + pr[i].z * w2.z + pr[i].w * w3.z;
                O[i][3] += pr[i].x * w0.w + pr[i].y * w1.w + pr[i].z * w2.w + pr[i].w * w3.w;
            }
        }
    }

    // normalize and write context
#pragma unroll
    for (int i = 0; i < 4; i++) {
        float inv = 1.f / l_i[i];
        float4 o;
        o.x = O[i][0] * inv; o.y = O[i][1] * inv;
        o.z = O[i][2] * inv; o.w = O[i][3] * inv;
        *(float4*)&g_ctx[(size_t)(q0 + ty * 4 + i) * DIM + hoff + tx * 4] = o;
    }
}

// ---------------- K6: LayerNorm ---------------------------------------------------
__global__ __launch_bounds__(256) void k_ln(const float* __restrict__ g,
                                            const float* __restrict__ b,
                                            float* __restrict__ out) {
    __shared__ float s1[8], s2[8], mv[2];
    int s = blockIdx.x, tid = threadIdx.x;
    const float* r = g_res + (size_t)s * DIM;
    float4 x = *(const float4*)(r + tid * 4);
    float sum = x.x + x.y + x.z + x.w;
    float sq = x.x * x.x + x.y * x.y + x.z * x.z + x.w * x.w;
#pragma unroll
    for (int o = 16; o; o >>= 1) {
        sum += __shfl_xor_sync(0xffffffffu, sum, o);
        sq  += __shfl_xor_sync(0xffffffffu, sq, o);
    }
    if ((tid & 31) == 0) { s1[tid >> 5] = sum; s2[tid >> 5] = sq; }
    __syncthreads();
    if (tid == 0) {
        float a = 0.f, c = 0.f;
#pragma unroll
        for (int i = 0; i < 8; i++) { a += s1[i]; c += s2[i]; }
        float mean = a * (1.f / DIM);
        float var = c * (1.f / DIM) - mean * mean;
        mv[0] = mean;
        mv[1] = rsqrtf(var + LNEPS);
    }
    __syncthreads();
    float mean = mv[0], rs = mv[1];
    int c0 = tid * 4;
    float4 gg = *(const float4*)(g + c0);
    float4 bb = *(const float4*)(b + c0);
    float4 o;
    o.x = (x.x - mean) * rs * gg.x + bb.x;
    o.y = (x.y - mean) * rs * gg.y + bb.y;
    o.z = (x.z - mean) * rs * gg.z + bb.z;
    o.w = (x.w - mean) * rs * gg.w + bb.w;
    *(float4*)(out + (size_t)s * DIM + c0) = o;
}

// ---------------- launch ----------------------------------------------------------
extern "C" void kernel_launch(void* const* d_in, const int* in_sizes, int n_in,
                              void* d_out, int out_size) {
    const float* hs  = (const float*)d_in[0];
    const float* Wq  = (const float*)d_in[1];  const float* bq  = (const float*)d_in[2];
    const float* Wk  = (const float*)d_in[3];  const float* bk  = (const float*)d_in[4];
    const float* Wv  = (const float*)d_in[5];  const float* bv  = (const float*)d_in[6];
    const float* Wo  = (const float*)d_in[7];  const float* bo  = (const float*)d_in[8];
    const float* Weq = (const float*)d_in[9];  const float* beq = (const float*)d_in[10];
    const float* Wek = (const float*)d_in[11]; const float* bek = (const float*)d_in[12];
    const float* aw  = (const float*)d_in[13]; const float* ab  = (const float*)d_in[14];
    const float* pw  = (const float*)d_in[15]; const float* pb  = (const float*)d_in[16];
    const float* mw  = (const float*)d_in[17]; const float* mb  = (const float*)d_in[18];
    const float* lg  = (const float*)d_in[19]; const float* lb  = (const float*)d_in[20];
    float* out = (float*)d_out;

    cudaFuncSetAttribute(k_attn, cudaFuncAttributeMaxDynamicSharedMemorySize,
                         ATTN_SMEM_BYTES);

    k_gemm5<<<dim3(8, 16, 5), 256>>>(hs, Wq, bq, Wk, bk, Wv, bv, Weq, beq, Wek, bek);
    k_ampph<<<2048, 256>>>(hs, aw, ab, pw, pb);
    k_mixed<<<dim3(64, 16), 256>>>(mw, mb);
    k_attn<<<dim3(32, 16), 256, ATTN_SMEM_BYTES>>>();
    k_gemmo<<<dim3(8, 16), 256>>>(hs, Wo, bo);
    k_ln<<<2048, 256>>>(lg, lb, out);
}

// round 2
// speedup vs baseline: 1.0500x; 1.0500x over previous
#include <cuda_runtime.h>

#define SEQ 2048
#define DIM 1024
#define NH 16
#define HDIM 64
#define SCALE 0.125f
#define ENTW 0.5f
#define DECAYC 0.1f
#define SUPW 0.3f
#define LNEPS 1e-5f
#define PI_F 3.14159265358979323846f

// ---------------- scratch (static device allocations are the sanctioned path) ----
__device__ float g_q[SEQ * DIM];
__device__ float g_k[SEQ * DIM];
__device__ float g_v[SEQ * DIM];
__device__ float g_eq[SEQ * DIM];
__device__ float g_ek[SEQ * DIM];
__device__ float g_mx[SEQ * DIM];   // mixed values
__device__ float g_ctx[SEQ * DIM];  // attention output (pre-Wo)
__device__ float g_res[SEQ * DIM];  // residual (pre-LN)
__device__ float g_ca[SEQ * NH];    // SUP * amp * cos(phase)
__device__ float g_sa[SEQ * NH];    // SUP * amp * sin(phase)

// ---------------- generic 128x128x16 fp32 tiled GEMM:  C = A @ W^T + bias (+resid)
// A: [M,1024] row-major, W: [N,1024] row-major, C: [M,1024] (we always have N,K=1024)
__device__ __forceinline__ void gemm128(const float* __restrict__ A,
                                        const float* __restrict__ W,
                                        const float* __restrict__ bias,
                                        const float* __restrict__ resid,
                                        float* __restrict__ C) {
    __shared__ __align__(16) float As[16][132];
    __shared__ __align__(16) float Bs[16][132];
    const int K = 1024;
    int m0 = blockIdx.y * 128;
    int n0 = blockIdx.x * 128;
    int tid = threadIdx.x;
    int tm = tid >> 4;   // 0..15
    int tn = tid & 15;   // 0..15

    float acc[8][8];
#pragma unroll
    for (int i = 0; i < 8; i++)
#pragma unroll
        for (int j = 0; j < 8; j++) acc[i][j] = 0.f;

    for (int k0 = 0; k0 < K; k0 += 16) {
#pragma unroll
        for (int t = 0; t < 2; t++) {
            int f = tid + (t << 8);       // 0..511
            int row = f >> 2;             // 0..127
            int kc = (f & 3) << 2;        // 0,4,8,12
            float4 a = *(const float4*)(A + (size_t)(m0 + row) * K + k0 + kc);
            As[kc + 0][row] = a.x; As[kc + 1][row] = a.y;
            As[kc + 2][row] = a.z; As[kc + 3][row] = a.w;
            float4 w = *(const float4*)(W + (size_t)(n0 + row) * K + k0 + kc);
            Bs[kc + 0][row] = w.x; Bs[kc + 1][row] = w.y;
            Bs[kc + 2][row] = w.z; Bs[kc + 3][row] = w.w;
        }
        __syncthreads();
#pragma unroll
        for (int kk = 0; kk < 16; kk++) {
            float a[8], b[8];
            *(float4*)(a)     = *(const float4*)&As[kk][tm * 8];
            *(float4*)(a + 4) = *(const float4*)&As[kk][tm * 8 + 4];
            *(float4*)(b)     = *(const float4*)&Bs[kk][tn * 8];
            *(float4*)(b + 4) = *(const float4*)&Bs[kk][tn * 8 + 4];
#pragma unroll
            for (int i = 0; i < 8; i++)
#pragma unroll
                for (int j = 0; j < 8; j++) acc[i][j] += a[i] * b[j];
        }
        __syncthreads();
    }

#pragma unroll
    for (int i = 0; i < 8; i++) {
        int row = m0 + tm * 8 + i;
#pragma unroll
        for (int jj = 0; jj < 8; jj += 4) {
            int col = n0 + tn * 8 + jj;
            float4 o;
            o.x = acc[i][jj + 0] + bias[col + 0];
            o.y = acc[i][jj + 1] + bias[col + 1];
            o.z = acc[i][jj + 2] + bias[col + 2];
            o.w = acc[i][jj + 3] + bias[col + 3];
            if (resid) {
                const float4 r = *(const float4*)(resid + (size_t)row * DIM + col);
                o.x += r.x; o.y += r.y; o.z += r.z; o.w += r.w;
            }
            *(float4*)(C + (size_t)row * DIM + col) = o;
        }
    }
}

// ---------------- K1: fused 5-way projection GEMM (Q,K,V,EQ,EK) ------------------
__global__ __launch_bounds__(256) void k_gemm5(
    const float* __restrict__ hs,
    const float* __restrict__ Wq, const float* __restrict__ bq,
    const float* __restrict__ Wk, const float* __restrict__ bk,
    const float* __restrict__ Wv, const float* __restrict__ bv,
    const float* __restrict__ Weq, const float* __restrict__ beq,
    const float* __restrict__ Wek, const float* __restrict__ bek) {
    const float* W; const float* b; float* C;
    switch (blockIdx.z) {
        case 0:  W = Wq;  b = bq;  C = g_q;  break;
        case 1:  W = Wk;  b = bk;  C = g_k;  break;
        case 2:  W = Wv;  b = bv;  C = g_v;  break;
        case 3:  W = Weq; b = beq; C = g_eq; break;
        default: W = Wek; b = bek; C = g_ek; break;
    }
    gemm128(hs, W, b, nullptr, C);
}

// ---------------- K5: output projection + residual -------------------------------
__global__ __launch_bounds__(256) void k_gemmo(const float* __restrict__ hs,
                                               const float* __restrict__ Wo,
                                               const float* __restrict__ bo) {
    gemm128(g_ctx, Wo, bo, hs, g_res);
}

// ---------------- K2: amplitudes & phases -> ca/sa --------------------------------
__global__ __launch_bounds__(256) void k_ampph(const float* __restrict__ hs,
                                               const float* __restrict__ aw,
                                               const float* __restrict__ ab,
                                               const float* __restrict__ pw,
                                               const float* __restrict__ pb) {
    __shared__ float row[DIM];
    __shared__ float acc[32];
    int s = blockIdx.x, tid = threadIdx.x;
    for (int i = tid; i < DIM; i += 256) row[i] = hs[(size_t)s * DIM + i];
    __syncthreads();
    int w = tid >> 5, lane = tid & 31;
#pragma unroll
    for (int t = 0; t < 4; t++) {
        int o = w * 4 + t;          // 0..31  (0..15 amp, 16..31 phase)
        int hh = o & 15;
        const float* wp = (o < 16) ? (aw + (size_t)hh * DIM) : (pw + (size_t)hh * DIM);
        float sum = 0.f;
        for (int i = lane; i < DIM; i += 32) sum += row[i] * wp[i];
#pragma unroll
        for (int m = 16; m; m >>= 1) sum += __shfl_xor_sync(0xffffffffu, sum, m);
        if (lane == 0) acc[o] = sum + ((o < 16) ? ab[hh] : pb[hh]);
    }
    __syncthreads();
    if (tid < NH) {
        float a = 1.f / (1.f + expf(-acc[tid]));
        float ph = tanhf(acc[16 + tid]) * PI_F;
        float sp, cp;
        sincosf(ph, &sp, &cp);
        g_ca[s * NH + tid] = SUPW * a * cp;
        g_sa[s * NH + tid] = SUPW * a * sp;
    }
}

// ---------------- K3: per-head superposition mixer -> g_mx ------------------------
__global__ __launch_bounds__(256) void k_mixed(const float* __restrict__ mw_g,
                                               const float* __restrict__ mb_g) {
    __shared__ float mw[64][65];
    __shared__ float vt[32][65];
    __shared__ float sp[32][65];
    __shared__ float mb[64];
    int h = blockIdx.y, s0 = blockIdx.x * 32;
    int tid = threadIdx.x;
    for (int i = tid; i < 4096; i += 256) mw[i >> 6][i & 63] = mw_g[h * 4096 + i];
    if (tid < 64) mb[tid] = mb_g[h * 64 + tid];
    for (int i = tid; i < 2048; i += 256)
        vt[i >> 6][i & 63] = g_v[(size_t)(s0 + (i >> 6)) * DIM + h * HDIM + (i & 63)];
    __syncthreads();

    int r = tid >> 3;            // 0..31
    int ob = (tid & 7) * 8;      // 0..56
    float a[8];
#pragma unroll
    for (int j = 0; j < 8; j++) a[j] = 0.f;
    for (int d = 0; d < 64; d++) {
        float vv = vt[r][d];
#pragma unroll
        for (int j = 0; j < 8; j++) a[j] += vv * mw[ob + j][d];
    }
#pragma unroll
    for (int j = 0; j < 8; j++) sp[r][ob + j] = a[j] + mb[ob + j];
    __syncthreads();

    for (int i = tid; i < 2048; i += 256) {
        int rr = i >> 6, o = i & 63;
        float ca = g_ca[(s0 + rr) * NH + h];
        float sa = g_sa[(s0 + rr) * NH + h];
        g_mx[(size_t)(s0 + rr) * DIM + h * HDIM + o] =
            vt[rr][o] + ca * sp[rr][o] + sa * sp[rr][(o + 63) & 63];
    }
}

// ---------------- K4: flash attention with entanglement + decay -------------------
// grid (32 q-tiles, 16 heads), 256 threads.  BM=BN=HD=64.
#define ASTR 68
#define ATTN_SMEM_BYTES ((6 * 64 * ASTR + 128) * 4)

__global__ __launch_bounds__(256, 2) void k_attn() {
    extern __shared__ __align__(16) float sm[];
    float* Qs = sm;
    float* Es = Qs + 64 * ASTR;
    float* Ks = Es + 64 * ASTR;
    float* Fs = Ks + 64 * ASTR;
    float* Ms = Fs + 64 * ASTR;
    float* Ps = Ms + 64 * ASTR;
    float* dtab = Ps + 64 * ASTR;

    int h = blockIdx.y;
    int q0 = blockIdx.x * 64;
    int tid = threadIdx.x;
    int ty = tid >> 4, tx = tid & 15;
    int hoff = h * HDIM;

    // load Q / EQ tiles once
#pragma unroll
    for (int t = 0; t < 4; t++) {
        int f = tid + (t << 8);
        int r = f >> 4, c = (f & 15) << 2;
        *(float4*)&Qs[r * ASTR + c] = *(const float4*)&g_q[(size_t)(q0 + r) * DIM + hoff + c];
        *(float4*)&Es[r * ASTR + c] = *(const float4*)&g_eq[(size_t)(q0 + r) * DIM + hoff + c];
    }

    float m_i[4], l_i[4], O[4][4];
#pragma unroll
    for (int i = 0; i < 4; i++) {
        m_i[i] = -1e30f; l_i[i] = 0.f;
#pragma unroll
        for (int j = 0; j < 4; j++) O[i][j] = 0.f;
    }

    for (int kt = 0; kt < 32; kt++) {
        int k0 = kt * 64;
        int dq = q0 - k0; int adq = dq < 0 ? -dq : dq;
        bool ent = (adq <= 384);   // beyond this decay < 1e-14 -> negligible

        __syncthreads();   // prev-iter PV done; (first iter) Q/EQ ready
#pragma unroll
        for (int t = 0; t < 4; t++) {
            int f = tid + (t << 8);
            int r = f >> 4, c = (f & 15) << 2;
            *(float4*)&Ks[r * ASTR + c] = *(const float4*)&g_k[(size_t)(k0 + r) * DIM + hoff + c];
            *(float4*)&Ms[r * ASTR + c] = *(const float4*)&g_mx[(size_t)(k0 + r) * DIM + hoff + c];
            if (ent)
                *(float4*)&Fs[r * ASTR + c] = *(const float4*)&g_ek[(size_t)(k0 + r) * DIM + hoff + c];
        }
        if (ent && tid < 127) {
            float dd = (float)(dq + tid - 63);   // (q0-k0) + (r-c)
            dtab[tid] = __expf(-DECAYC * fabsf(dd));
        }
        __syncthreads();

        float acc1[4][4], acc2[4][4];
#pragma unroll
        for (int i = 0; i < 4; i++)
#pragma unroll
            for (int j = 0; j < 4; j++) { acc1[i][j] = 0.f; acc2[i][j] = 0.f; }

        if (ent) {
#pragma unroll
            for (int d = 0; d < 64; d += 4) {
                float4 q[4], e[4];
#pragma unroll
                for (int i = 0; i < 4; i++) {
                    q[i] = *(const float4*)&Qs[(ty * 4 + i) * ASTR + d];
                    e[i] = *(const float4*)&Es[(ty * 4 + i) * ASTR + d];
                }
#pragma unroll
                for (int j = 0; j < 4; j++) {
                    float4 k = *(const float4*)&Ks[(tx + 16 * j) * ASTR + d];
                    float4 f = *(const float4*)&Fs[(tx + 16 * j) * ASTR + d];
#pragma unroll
                    for (int i = 0; i < 4; i++) {
                        acc1[i][j] += q[i].x * k.x + q[i].y * k.y + q[i].z * k.z + q[i].w * k.w;
                        acc2[i][j] += e[i].x * f.x + e[i].y * f.y + e[i].z * f.z + e[i].w * f.w;
                    }
                }
            }
        } else {
#pragma unroll
            for (int d = 0; d < 64; d += 4) {
                float4 q[4];
#pragma unroll
                for (int i = 0; i < 4; i++)
                    q[i] = *(const float4*)&Qs[(ty * 4 + i) * ASTR + d];
#pragma unroll
                for (int j = 0; j < 4; j++) {
                    float4 k = *(const float4*)&Ks[(tx + 16 * j) * ASTR + d];
#pragma unroll
                    for (int i = 0; i < 4; i++)
                        acc1[i][j] += q[i].x * k.x + q[i].y * k.y + q[i].z * k.z + q[i].w * k.w;
                }
            }
        }

        // online softmax over this key tile
#pragma unroll
        for (int i = 0; i < 4; i++) {
            int rr = ty * 4 + i;
            float sv[4];
            float mx = -1e30f;
#pragma unroll
            for (int j = 0; j < 4; j++) {
                int cc = tx + 16 * j;
                float s = SCALE * acc1[i][j];
                if (ent) s += (ENTW * SCALE) * dtab[rr - cc + 63] * acc2[i][j];
                sv[j] = s;
                mx = fmaxf(mx, s);
            }
#pragma unroll
            for (int o = 1; o < 16; o <<= 1)
                mx = fmaxf(mx, __shfl_xor_sync(0xffffffffu, mx, o));
            float mnew = fmaxf(m_i[i], mx);
            float alpha = __expf(m_i[i] - mnew);
            float sum = 0.f;
#pragma unroll
            for (int j = 0; j < 4; j++) {
                float p = __expf(sv[j] - mnew);
                Ps[rr * ASTR + tx + 16 * j] = p;
                sum += p;
            }
#pragma unroll
            for (int o = 1; o < 16; o <<= 1)
                sum += __shfl_xor_sync(0xffffffffu, sum, o);
            l_i[i] = l_i[i] * alpha + sum;
            m_i[i] = mnew;
#pragma unroll
            for (int j = 0; j < 4; j++) O[i][j] *= alpha;
        }
        __syncthreads();

        // O += P @ Mixed   (O columns = tx*4 + j)
#pragma unroll
        for (int c = 0; c < 64; c += 4) {
            float4 pr[4];
#pragma unroll
            for (int i = 0; i < 4; i++)
                pr[i] = *(const float4*)&Ps[(ty * 4 + i) * ASTR + c];
            float4 w0 = *(const float4*)&Ms[(c + 0) * ASTR + tx * 4];
            float4 w1 = *(const float4*)&Ms[(c + 1) * ASTR + tx * 4];
            float4 w2 = *(const float4*)&Ms[(c + 2) * ASTR + tx * 4];
            float4 w3 = *(const float4*)&Ms[(c + 3) * ASTR + tx * 4];
#pragma unroll
            for (int i = 0; i < 4; i++) {
                O[i][0] += pr[i].x * w0.x + pr[i].y * w1.x + pr[i].z * w2.x + pr[i].w * w3.x;
                O[i][1] += pr[i].x * w0.y + pr[i].y * w1.y + pr[i].z * w2.y + pr[i].w * w3.y;
                O[i][2] += pr[i].x * w0.z + pr[i].y * w1.z + pr[i].z * w2.z + pr[i].w * w3.z;
                O[i][3] += pr[i].x * w0.w + pr[i].y * w1.w + pr[i].z * w2.w + pr[i].w * w3.w;
            }
        }
    }

    // normalize and write context
#pragma unroll
    for (int i = 0; i < 4; i++) {
        float inv = 1.f / l_i[i];
        float4 o;
        o.x = O[i][0] * inv; o.y = O[i][1] * inv;
        o.z = O[i][2] * inv; o.w = O[i][3] * inv;
        *(float4*)&g_ctx[(size_t)(q0 + ty * 4 + i) * DIM + hoff + tx * 4] = o;
    }
}

// ---------------- K6: LayerNorm ---------------------------------------------------
__global__ __launch_bounds__(256) void k_ln(const float* __restrict__ g,
                                            const float* __restrict__ b,
                                            float* __restrict__ out) {
    __shared__ float s1[8], s2[8], mv[2];
    int s = blockIdx.x, tid = threadIdx.x;
    const float* r = g_res + (size_t)s * DIM;
    float4 x = *(const float4*)(r + tid * 4);
    float sum = x.x + x.y + x.z + x.w;
    float sq = x.x * x.x + x.y * x.y + x.z * x.z + x.w * x.w;
#pragma unroll
    for (int o = 16; o; o >>= 1) {
        sum += __shfl_xor_sync(0xffffffffu, sum, o);
        sq  += __shfl_xor_sync(0xffffffffu, sq, o);
    }
    if ((tid & 31) == 0) { s1[tid >> 5] = sum; s2[tid >> 5] = sq; }
    __syncthreads();
    if (tid == 0) {
        float a = 0.f, c = 0.f;
#pragma unroll
        for (int i = 0; i < 8; i++) { a += s1[i]; c += s2[i]; }
        float mean = a * (1.f / DIM);
        float var = c * (1.f / DIM) - mean * mean;
        mv[0] = mean;
        mv[1] = rsqrtf(var + LNEPS);
    }
    __syncthreads();
    float mean = mv[0], rs = mv[1];
    int c0 = tid * 4;
    float4 gg = *(const float4*)(g + c0);
    float4 bb = *(const float4*)(b + c0);
    float4 o;
    o.x = (x.x - mean) * rs * gg.x + bb.x;
    o.y = (x.y - mean) * rs * gg.y + bb.y;
    o.z = (x.z - mean) * rs * gg.z + bb.z;
    o.w = (x.w - mean) * rs * gg.w + bb.w;
    *(float4*)(out + (size_t)s * DIM + c0) = o;
}

// ---------------- launch ----------------------------------------------------------
extern "C" void kernel_launch(void* const* d_in, const int* in_sizes, int n_in,
                              void* d_out, int out_size) {
    const float* hs  = (const float*)d_in[0];
    const float* Wq  = (const float*)d_in[1];  const float* bq  = (const float*)d_in[2];
    const float* Wk  = (const float*)d_in[3];  const float* bk  = (const float*)d_in[4];
    const float* Wv  = (const float*)d_in[5];  const float* bv  = (const float*)d_in[6];
    const float* Wo  = (const float*)d_in[7];  const float* bo  = (const float*)d_in[8];
    const float* Weq = (const float*)d_in[9];  const float* beq = (const float*)d_in[10];
    const float* Wek = (const float*)d_in[11]; const float* bek = (const float*)d_in[12];
    const float* aw  = (const float*)d_in[13]; const float* ab  = (const float*)d_in[14];
    const float* pw  = (const float*)d_in[15]; const float* pb  = (const float*)d_in[16];
    const float* mw  = (const float*)d_in[17]; const float* mb  = (const float*)d_in[18];
    const float* lg  = (const float*)d_in[19]; const float* lb  = (const float*)d_in[20];
    float* out = (float*)d_out;

    cudaFuncSetAttribute(k_attn, cudaFuncAttributeMaxDynamicSharedMemorySize,
                         ATTN_SMEM_BYTES);

    k_gemm5<<<dim3(8, 16, 5), 256>>>(hs, Wq, bq, Wk, bk, Wv, bv, Weq, beq, Wek, bek);
    k_ampph<<<2048, 256>>>(hs, aw, ab, pw, pb);
    k_mixed<<<dim3(64, 16), 256>>>(mw, mb);
    k_attn<<<dim3(32, 16), 256, ATTN_SMEM_BYTES>>>();
    k_gemmo<<<dim3(8, 16), 256>>>(hs, Wo, bo);
    k_ln<<<2048, 256>>>(lg, lb, out);
}

// round 4
// speedup vs baseline: 1.4181x; 1.3506x over previous
#include <cuda_runtime.h>
#include <cuda_bf16.h>

#define SEQ 2048
#define DIM 1024
#define NH 16
#define HDIM 64
#define SCALE 0.125f
#define ENTW 0.5f
#define DECAYC 0.1f
#define SUPW 0.3f
#define LNEPS 1e-5f
#define PI_F 3.14159265358979323846f

// ---------------- scratch ----------------
__device__ float g_q[SEQ * DIM];
__device__ float g_k[SEQ * DIM];
__device__ float g_v[SEQ * DIM];
__device__ float g_eq[SEQ * DIM];
__device__ float g_ek[SEQ * DIM];
__device__ float g_mx[SEQ * DIM];
__device__ float g_ctx[SEQ * DIM];
__device__ float g_res[SEQ * DIM];
__device__ float g_ca[SEQ * NH];
__device__ float g_sa[SEQ * NH];
__device__ __nv_bfloat16 g_ah[SEQ * DIM];
__device__ __nv_bfloat16 g_al[SEQ * DIM];
__device__ __nv_bfloat16 g_wh[6 * DIM * DIM];
__device__ __nv_bfloat16 g_wl[6 * DIM * DIM];

// ---------------- helpers ----------------
__device__ __forceinline__ unsigned smem_u32(const void* p) {
    unsigned a;
    asm("{ .reg .u64 t; cvta.to.shared.u64 t, %1; cvt.u32.u64 %0, t; }" : "=r"(a) : "l"(p));
    return a;
}
__device__ __forceinline__ void cp16(unsigned d, const void* s) {
    asm volatile("cp.async.cg.shared.global [%0], [%1], 16;" :: "r"(d), "l"(s));
}
__device__ __forceinline__ void ldm4(unsigned* r, unsigned a) {
    asm volatile("ldmatrix.sync.aligned.m8n8.x4.shared.b16 {%0,%1,%2,%3}, [%4];"
        : "=r"(r[0]), "=r"(r[1]), "=r"(r[2]), "=r"(r[3]) : "r"(a));
}
__device__ __forceinline__ void mmabf(float* d, const unsigned* a, const unsigned* b) {
    asm volatile(
        "mma.sync.aligned.m16n8k16.row.col.f32.bf16.bf16.f32 "
        "{%0,%1,%2,%3}, {%4,%5,%6,%7}, {%8,%9}, {%0,%1,%2,%3};"
        : "+f"(d[0]), "+f"(d[1]), "+f"(d[2]), "+f"(d[3])
        : "r"(a[0]), "r"(a[1]), "r"(a[2]), "r"(a[3]), "r"(b[0]), "r"(b[1]));
}

// ---------------- split-precision conversion ----------------
__global__ __launch_bounds__(256) void k_cvt(const float* __restrict__ s,
                                             __nv_bfloat16* __restrict__ hi,
                                             __nv_bfloat16* __restrict__ lo, int n4) {
    int i = blockIdx.x * 256 + threadIdx.x;
    if (i >= n4) return;
    float4 x = ((const float4*)s)[i];
    __nv_bfloat16 h0 = __float2bfloat16(x.x);
    __nv_bfloat16 h1 = __float2bfloat16(x.y);
    __nv_bfloat16 h2 = __float2bfloat16(x.z);
    __nv_bfloat16 h3 = __float2bfloat16(x.w);
    __nv_bfloat16 l0 = __float2bfloat16(x.x - __bfloat162float(h0));
    __nv_bfloat16 l1 = __float2bfloat16(x.y - __bfloat162float(h1));
    __nv_bfloat16 l2 = __float2bfloat16(x.z - __bfloat162float(h2));
    __nv_bfloat16 l3 = __float2bfloat16(x.w - __bfloat162float(h3));
    ((__nv_bfloat162*)hi)[i * 2]     = __nv_bfloat162(h0, h1);
    ((__nv_bfloat162*)hi)[i * 2 + 1] = __nv_bfloat162(h2, h3);
    ((__nv_bfloat162*)lo)[i * 2]     = __nv_bfloat162(l0, l1);
    ((__nv_bfloat162*)lo)[i * 2 + 1] = __nv_bfloat162(l2, l3);
}

// ---------------- mma.sync bf16-split GEMM ----------------
// C[128x128 tile] = A @ W^T + bias (+resid); A,W split hi/lo; K=1024, chunk 32.
#define RSTR 40                 // padded row stride in bf16 (conflict-free ldmatrix)
#define PLANE 10240             // 128*RSTR*2 bytes per plane
#define STAGE (4 * PLANE)       // Ah, Al, Bh, Bl
#define GSMEM (2 * STAGE)       // 81920 B

__device__ __forceinline__ void load_chunk(unsigned st,
        const __nv_bfloat16* __restrict__ Ah, const __nv_bfloat16* __restrict__ Al,
        const __nv_bfloat16* __restrict__ Bh, const __nv_bfloat16* __restrict__ Bl,
        int m0, int n0, int k0, int tid) {
#pragma unroll
    for (int i = 0; i < 8; i++) {
        int idx = i * 256 + tid;           // 0..2047
        int plane = idx >> 9;              // 0..3
        int row = (idx >> 2) & 127;
        int ck = idx & 3;                  // 16B chunk within 64B row
        unsigned soff = st + plane * PLANE + (unsigned)(row * RSTR + ck * 8) * 2;
        const __nv_bfloat16* gp;
        if      (plane == 0) gp = Ah + (size_t)(m0 + row) * DIM + k0 + ck * 8;
        else if (plane == 1) gp = Al + (size_t)(m0 + row) * DIM + k0 + ck * 8;
        else if (plane == 2) gp = Bh + (size_t)(n0 + row) * DIM + k0 + ck * 8;
        else                 gp = Bl + (size_t)(n0 + row) * DIM + k0 + ck * 8;
        cp16(soff, gp);
    }
    asm volatile("cp.async.commit_group;" ::: "memory");
}

__device__ __forceinline__ void gemm_mma(
        const __nv_bfloat16* __restrict__ Ah, const __nv_bfloat16* __restrict__ Al,
        const __nv_bfloat16* __restrict__ Wh, const __nv_bfloat16* __restrict__ Wl,
        const float* __restrict__ bias, const float* __restrict__ resid,
        float* __restrict__ C) {
    extern __shared__ char dynsm[];
    unsigned sb = smem_u32(dynsm);
    int tid = threadIdx.x, lane = tid & 31, w = tid >> 5;
    int wm = w & 1, wn = w >> 1;               // 2 x 4 warps
    int m0 = blockIdx.y * 128, n0 = blockIdx.x * 128;

    float acc[4][4][4];
#pragma unroll
    for (int a = 0; a < 4; a++)
#pragma unroll
        for (int b = 0; b < 4; b++)
#pragma unroll
            for (int d = 0; d < 4; d++) acc[a][b][d] = 0.f;

    load_chunk(sb, Ah, Al, Wh, Wl, m0, n0, 0, tid);

    // ldmatrix lane mappings
    int lrA = lane & 15;
    int lcA = (lane >> 4) << 3;
    int lnB = (lane & 7) + ((lane >> 4) << 3);
    int lkB = ((lane >> 3) & 1) << 3;
    unsigned aRow = (unsigned)((wm * 64 + lrA) * RSTR) * 2;
    unsigned bRow = (unsigned)((wn * 32 + lnB) * RSTR) * 2;

    for (int c = 0; c < 32; c++) {
        asm volatile("cp.async.wait_group 0;" ::: "memory");
        __syncthreads();
        if (c < 31)
            load_chunk(sb + ((c + 1) & 1) * STAGE, Ah, Al, Wh, Wl,
                       m0, n0, (c + 1) * 32, tid);
        unsigned st = sb + (c & 1) * STAGE;
#pragma unroll
        for (int ks = 0; ks < 32; ks += 16) {
            unsigned ah[4][4], al2[4][4], bh[4][2], bl2[4][2];
#pragma unroll
            for (int mt = 0; mt < 4; mt++) {
                unsigned ad = st + aRow + (unsigned)(mt * 16 * RSTR + ks + lcA) * 2;
                ldm4(ah[mt], ad);
                ldm4(al2[mt], ad + PLANE);
            }
#pragma unroll
            for (int p = 0; p < 2; p++) {
                unsigned bd = st + 2 * PLANE + bRow +
                              (unsigned)(p * 16 * RSTR + ks + lkB) * 2;
                unsigned t[4];
                ldm4(t, bd);
                bh[2 * p][0] = t[0]; bh[2 * p][1] = t[1];
                bh[2 * p + 1][0] = t[2]; bh[2 * p + 1][1] = t[3];
                ldm4(t, bd + PLANE);
                bl2[2 * p][0] = t[0]; bl2[2 * p][1] = t[1];
                bl2[2 * p + 1][0] = t[2]; bl2[2 * p + 1][1] = t[3];
            }
#pragma unroll
            for (int mt = 0; mt < 4; mt++)
#pragma unroll
                for (int nt = 0; nt < 4; nt++) {
                    mmabf(acc[mt][nt], ah[mt], bh[nt]);
                    mmabf(acc[mt][nt], ah[mt], bl2[nt]);
                    mmabf(acc[mt][nt], al2[mt], bh[nt]);
                }
        }
        __syncthreads();
    }

    // epilogue: direct stores with bias/resid
    int r0 = m0 + wm * 64 + (lane >> 2);
    int cb = n0 + wn * 32 + (lane & 3) * 2;
#pragma unroll
    for (int mt = 0; mt < 4; mt++) {
#pragma unroll
        for (int nt = 0; nt < 4; nt++) {
            int rr = r0 + mt * 16;
            int cc = cb + nt * 8;
            float b0 = bias[cc], b1 = bias[cc + 1];
            float2 v0 = make_float2(acc[mt][nt][0] + b0, acc[mt][nt][1] + b1);
            float2 v1 = make_float2(acc[mt][nt][2] + b0, acc[mt][nt][3] + b1);
            if (resid) {
                const float2 q0 = *(const float2*)(resid + (size_t)rr * DIM + cc);
                const float2 q1 = *(const float2*)(resid + (size_t)(rr + 8) * DIM + cc);
                v0.x += q0.x; v0.y += q0.y;
                v1.x += q1.x; v1.y += q1.y;
            }
            *(float2*)(C + (size_t)rr * DIM + cc) = v0;
            *(float2*)(C + (size_t)(rr + 8) * DIM + cc) = v1;
        }
    }
}

__global__ __launch_bounds__(256) void k_proj5(
        const float* __restrict__ bq, const float* __restrict__ bk,
        const float* __restrict__ bv, const float* __restrict__ beq,
        const float* __restrict__ bek) {
    int z = blockIdx.z;
    const float* bias; float* C;
    switch (z) {
        case 0:  bias = bq;  C = g_q;  break;
        case 1:  bias = bk;  C = g_k;  break;
        case 2:  bias = bv;  C = g_v;  break;
        case 3:  bias = beq; C = g_eq; break;
        default: bias = bek; C = g_ek; break;
    }
    gemm_mma(g_ah, g_al, g_wh + (size_t)z * DIM * DIM, g_wl + (size_t)z * DIM * DIM,
             bias, nullptr, C);
}

__global__ __launch_bounds__(256) void k_wo(const float* __restrict__ bo,
                                            const float* __restrict__ hs) {
    gemm_mma(g_ah, g_al, g_wh + 5ull * DIM * DIM, g_wl + 5ull * DIM * DIM, bo, hs, g_res);
}

// ---------------- K2: amplitudes & phases ----------------
__global__ __launch_bounds__(256) void k_ampph(const float* __restrict__ hs,
                                               const float* __restrict__ aw,
                                               const float* __restrict__ ab,
                                               const float* __restrict__ pw,
                                               const float* __restrict__ pb) {
    __shared__ float row[DIM];
    __shared__ float acc[32];
    int s = blockIdx.x, tid = threadIdx.x;
    for (int i = tid; i < DIM; i += 256) row[i] = hs[(size_t)s * DIM + i];
    __syncthreads();
    int w = tid >> 5, lane = tid & 31;
#pragma unroll
    for (int t = 0; t < 4; t++) {
        int o = w * 4 + t;
        int hh = o & 15;
        const float* wp = (o < 16) ? (aw + (size_t)hh * DIM) : (pw + (size_t)hh * DIM);
        float sum = 0.f;
        for (int i = lane; i < DIM; i += 32) sum += row[i] * wp[i];
#pragma unroll
        for (int m = 16; m; m >>= 1) sum += __shfl_xor_sync(0xffffffffu, sum, m);
        if (lane == 0) acc[o] = sum + ((o < 16) ? ab[hh] : pb[hh]);
    }
    __syncthreads();
    if (tid < NH) {
        float a = 1.f / (1.f + expf(-acc[tid]));
        float ph = tanhf(acc[16 + tid]) * PI_F;
        float sp, cp;
        sincosf(ph, &sp, &cp);
        g_ca[s * NH + tid] = SUPW * a * cp;
        g_sa[s * NH + tid] = SUPW * a * sp;
    }
}

// ---------------- K3: per-head superposition mixer ----------------
__global__ __launch_bounds__(256) void k_mixed(const float* __restrict__ mw_g,
                                               const float* __restrict__ mb_g) {
    __shared__ float mw[64][65];
    __shared__ float vt[32][65];
    __shared__ float sp[32][65];
    __shared__ float mb[64];
    int h = blockIdx.y, s0 = blockIdx.x * 32;
    int tid = threadIdx.x;
    for (int i = tid; i < 4096; i += 256) mw[i >> 6][i & 63] = mw_g[h * 4096 + i];
    if (tid < 64) mb[tid] = mb_g[h * 64 + tid];
    for (int i = tid; i < 2048; i += 256)
        vt[i >> 6][i & 63] = g_v[(size_t)(s0 + (i >> 6)) * DIM + h * HDIM + (i & 63)];
    __syncthreads();

    int r = tid >> 3;
    int ob = (tid & 7) * 8;
    float a[8];
#pragma unroll
    for (int j = 0; j < 8; j++) a[j] = 0.f;
    for (int d = 0; d < 64; d++) {
        float vv = vt[r][d];
#pragma unroll
        for (int j = 0; j < 8; j++) a[j] += vv * mw[ob + j][d];
    }
#pragma unroll
    for (int j = 0; j < 8; j++) sp[r][ob + j] = a[j] + mb[ob + j];
    __syncthreads();

    for (int i = tid; i < 2048; i += 256) {
        int rr = i >> 6, o = i & 63;
        float ca = g_ca[(s0 + rr) * NH + h];
        float sa = g_sa[(s0 + rr) * NH + h];
        g_mx[(size_t)(s0 + rr) * DIM + h * HDIM + o] =
            vt[rr][o] + ca * sp[rr][o] + sa * sp[rr][(o + 63) & 63];
    }
}

// ---------------- K4: flash attention (fp32, proven) ----------------
#define ASTR 68
#define ATTN_SMEM_BYTES ((6 * 64 * ASTR + 128) * 4)

__global__ __launch_bounds__(256, 2) void k_attn() {
    extern __shared__ __align__(16) float sm[];
    float* Qs = sm;
    float* Es = Qs + 64 * ASTR;
    float* Ks = Es + 64 * ASTR;
    float* Fs = Ks + 64 * ASTR;
    float* Ms = Fs + 64 * ASTR;
    float* Ps = Ms + 64 * ASTR;
    float* dtab = Ps + 64 * ASTR;

    int h = blockIdx.y;
    int q0 = blockIdx.x * 64;
    int tid = threadIdx.x;
    int ty = tid >> 4, tx = tid & 15;
    int hoff = h * HDIM;

#pragma unroll
    for (int t = 0; t < 4; t++) {
        int f = tid + (t << 8);
        int r = f >> 4, c = (f & 15) << 2;
        *(float4*)&Qs[r * ASTR + c] = *(const float4*)&g_q[(size_t)(q0 + r) * DIM + hoff + c];
        *(float4*)&Es[r * ASTR + c] = *(const float4*)&g_eq[(size_t)(q0 + r) * DIM + hoff + c];
    }

    float m_i[4], l_i[4], O[4][4];
#pragma unroll
    for (int i = 0; i < 4; i++) {
        m_i[i] = -1e30f; l_i[i] = 0.f;
#pragma unroll
        for (int j = 0; j < 4; j++) O[i][j] = 0.f;
    }

    for (int kt = 0; kt < 32; kt++) {
        int k0 = kt * 64;
        int dq = q0 - k0; int adq = dq < 0 ? -dq : dq;
        bool ent = (adq <= 384);

        __syncthreads();
#pragma unroll
        for (int t = 0; t < 4; t++) {
            int f = tid + (t << 8);
            int r = f >> 4, c = (f & 15) << 2;
            *(float4*)&Ks[r * ASTR + c] = *(const float4*)&g_k[(size_t)(k0 + r) * DIM + hoff + c];
            *(float4*)&Ms[r * ASTR + c] = *(const float4*)&g_mx[(size_t)(k0 + r) * DIM + hoff + c];
            if (ent)
                *(float4*)&Fs[r * ASTR + c] = *(const float4*)&g_ek[(size_t)(k0 + r) * DIM + hoff + c];
        }
        if (ent && tid < 127) {
            float dd = (float)(dq + tid - 63);
            dtab[tid] = __expf(-DECAYC * fabsf(dd));
        }
        __syncthreads();

        float acc1[4][4], acc2[4][4];
#pragma unroll
        for (int i = 0; i < 4; i++)
#pragma unroll
            for (int j = 0; j < 4; j++) { acc1[i][j] = 0.f; acc2[i][j] = 0.f; }

        if (ent) {
#pragma unroll
            for (int d = 0; d < 64; d += 4) {
                float4 q[4], e[4];
#pragma unroll
                for (int i = 0; i < 4; i++) {
                    q[i] = *(const float4*)&Qs[(ty * 4 + i) * ASTR + d];
                    e[i] = *(const float4*)&Es[(ty * 4 + i) * ASTR + d];
                }
#pragma unroll
                for (int j = 0; j < 4; j++) {
                    float4 k = *(const float4*)&Ks[(tx + 16 * j) * ASTR + d];
                    float4 f = *(const float4*)&Fs[(tx + 16 * j) * ASTR + d];
#pragma unroll
                    for (int i = 0; i < 4; i++) {
                        acc1[i][j] += q[i].x * k.x + q[i].y * k.y + q[i].z * k.z + q[i].w * k.w;
                        acc2[i][j] += e[i].x * f.x + e[i].y * f.y + e[i].z * f.z + e[i].w * f.w;
                    }
                }
            }
        } else {
#pragma unroll
            for (int d = 0; d < 64; d += 4) {
                float4 q[4];
#pragma unroll
                for (int i = 0; i < 4; i++)
                    q[i] = *(const float4*)&Qs[(ty * 4 + i) * ASTR + d];
#pragma unroll
                for (int j = 0; j < 4; j++) {
                    float4 k = *(const float4*)&Ks[(tx + 16 * j) * ASTR + d];
#pragma unroll
                    for (int i = 0; i < 4; i++)
                        acc1[i][j] += q[i].x * k.x + q[i].y * k.y + q[i].z * k.z + q[i].w * k.w;
                }
            }
        }

#pragma unroll
        for (int i = 0; i < 4; i++) {
            int rr = ty * 4 + i;
            float sv[4];
            float mx = -1e30f;
#pragma unroll
            for (int j = 0; j < 4; j++) {
                int cc = tx + 16 * j;
                float s = SCALE * acc1[i][j];
                if (ent) s += (ENTW * SCALE) * dtab[rr - cc + 63] * acc2[i][j];
                sv[j] = s;
                mx = fmaxf(mx, s);
            }
#pragma unroll
            for (int o = 1; o < 16; o <<= 1)
                mx = fmaxf(mx, __shfl_xor_sync(0xffffffffu, mx, o));
            float mnew = fmaxf(m_i[i], mx);
            float alpha = __expf(m_i[i] - mnew);
            float sum = 0.f;
#pragma unroll
            for (int j = 0; j < 4; j++) {
                float p = __expf(sv[j] - mnew);
                Ps[rr * ASTR + tx + 16 * j] = p;
                sum += p;
            }
#pragma unroll
            for (int o = 1; o < 16; o <<= 1)
                sum += __shfl_xor_sync(0xffffffffu, sum, o);
            l_i[i] = l_i[i] * alpha + sum;
            m_i[i] = mnew;
#pragma unroll
            for (int j = 0; j < 4; j++) O[i][j] *= alpha;
        }
        __syncthreads();

#pragma unroll
        for (int c = 0; c < 64; c += 4) {
            float4 pr[4];
#pragma unroll
            for (int i = 0; i < 4; i++)
                pr[i] = *(const float4*)&Ps[(ty * 4 + i) * ASTR + c];
            float4 w0 = *(const float4*)&Ms[(c + 0) * ASTR + tx * 4];
            float4 w1 = *(const float4*)&Ms[(c + 1) * ASTR + tx * 4];
            float4 w2 = *(const float4*)&Ms[(c + 2) * ASTR + tx * 4];
            float4 w3 = *(const float4*)&Ms[(c + 3) * ASTR + tx * 4];
#pragma unroll
            for (int i = 0; i < 4; i++) {
                O[i][0] += pr[i].x * w0.x + pr[i].y * w1.x + pr[i].z * w2.x + pr[i].w * w3.x;
                O[i][1] += pr[i].x * w0.y + pr[i].y * w1.y + pr[i].z * w2.y + pr[i].w * w3.y;
                O[i][2] += pr[i].x * w0.z + pr[i].y * w1.z + pr[i].z * w2.z + pr[i].w * w3.z;
                O[i][3] += pr[i].x * w0.w + pr[i].y * w1.w + pr[i].z * w2.w + pr[i].w * w3.w;
            }
        }
    }

#pragma unroll
    for (int i = 0; i < 4; i++) {
        float inv = 1.f / l_i[i];
        float4 o;
        o.x = O[i][0] * inv; o.y = O[i][1] * inv;
        o.z = O[i][2] * inv; o.w = O[i][3] * inv;
        *(float4*)&g_ctx[(size_t)(q0 + ty * 4 + i) * DIM + hoff + tx * 4] = o;
    }
}

// ---------------- K6: LayerNorm ----------------
__global__ __launch_bounds__(256) void k_ln(const float* __restrict__ g,
                                            const float* __restrict__ b,
                                            float* __restrict__ out) {
    __shared__ float s1[8], s2[8], mv[2];
    int s = blockIdx.x, tid = threadIdx.x;
    const float* r = g_res + (size_t)s * DIM;
    float4 x = *(const float4*)(r + tid * 4);
    float sum = x.x + x.y + x.z + x.w;
    float sq = x.x * x.x + x.y * x.y + x.z * x.z + x.w * x.w;
#pragma unroll
    for (int o = 16; o; o >>= 1) {
        sum += __shfl_xor_sync(0xffffffffu, sum, o);
        sq  += __shfl_xor_sync(0xffffffffu, sq, o);
    }
    if ((tid & 31) == 0) { s1[tid >> 5] = sum; s2[tid >> 5] = sq; }
    __syncthreads();
    if (tid == 0) {
        float a = 0.f, c = 0.f;
#pragma unroll
        for (int i = 0; i < 8; i++) { a += s1[i]; c += s2[i]; }
        float mean = a * (1.f / DIM);
        float var = c * (1.f / DIM) - mean * mean;
        mv[0] = mean;
        mv[1] = rsqrtf(var + LNEPS);
    }
    __syncthreads();
    float mean = mv[0], rs = mv[1];
    int c0 = tid * 4;
    float4 gg = *(const float4*)(g + c0);
    float4 bb = *(const float4*)(b + c0);
    float4 o;
    o.x = (x.x - mean) * rs * gg.x + bb.x;
    o.y = (x.y - mean) * rs * gg.y + bb.y;
    o.z = (x.z - mean) * rs * gg.z + bb.z;
    o.w = (x.w - mean) * rs * gg.w + bb.w;
    *(float4*)(out + (size_t)s * DIM + c0) = o;
}

// ---------------- launch ----------------
extern "C" void kernel_launch(void* const* d_in, const int* in_sizes, int n_in,
                              void* d_out, int out_size) {
    const float* hs  = (const float*)d_in[0];
    const float* Wq  = (const float*)d_in[1];  const float* bq  = (const float*)d_in[2];
    const float* Wk  = (const float*)d_in[3];  const float* bk  = (const float*)d_in[4];
    const float* Wv  = (const float*)d_in[5];  const float* bv  = (const float*)d_in[6];
    const float* Wo  = (const float*)d_in[7];  const float* bo  = (const float*)d_in[8];
    const float* Weq = (const float*)d_in[9];  const float* beq = (const float*)d_in[10];
    const float* Wek = (const float*)d_in[11]; const float* bek = (const float*)d_in[12];
    const float* aw  = (const float*)d_in[13]; const float* ab  = (const float*)d_in[14];
    const float* pw  = (const float*)d_in[15]; const float* pb  = (const float*)d_in[16];
    const float* mw  = (const float*)d_in[17]; const float* mb  = (const float*)d_in[18];
    const float* lg  = (const float*)d_in[19]; const float* lb  = (const float*)d_in[20];
    float* out = (float*)d_out;

    static __nv_bfloat16* wh_p = nullptr;
    static __nv_bfloat16* wl_p = nullptr;
    static __nv_bfloat16* ah_p = nullptr;
    static __nv_bfloat16* al_p = nullptr;
    static float* ctx_p = nullptr;
    if (!wh_p) {
        cudaGetSymbolAddress((void**)&wh_p, g_wh);
        cudaGetSymbolAddress((void**)&wl_p, g_wl);
        cudaGetSymbolAddress((void**)&ah_p, g_ah);
        cudaGetSymbolAddress((void**)&al_p, g_al);
        cudaGetSymbolAddress((void**)&ctx_p, g_ctx);
        cudaFuncSetAttribute(k_attn, cudaFuncAttributeMaxDynamicSharedMemorySize,
                             ATTN_SMEM_BYTES);
        cudaFuncSetAttribute(k_proj5, cudaFuncAttributeMaxDynamicSharedMemorySize, GSMEM);
        cudaFuncSetAttribute(k_wo, cudaFuncAttributeMaxDynamicSharedMemorySize, GSMEM);
    }

    const int WN4 = DIM * DIM / 4;     // 262144
    const int AN4 = SEQ * DIM / 4;     // 524288

    k_cvt<<<(AN4 + 255) / 256, 256>>>(hs, ah_p, al_p, AN4);
    k_cvt<<<(WN4 + 255) / 256, 256>>>(Wq,  wh_p + 0ull * DIM * DIM, wl_p + 0ull * DIM * DIM, WN4);
    k_cvt<<<(WN4 + 255) / 256, 256>>>(Wk,  wh_p + 1ull * DIM * DIM, wl_p + 1ull * DIM * DIM, WN4);
    k_cvt<<<(WN4 + 255) / 256, 256>>>(Wv,  wh_p + 2ull * DIM * DIM, wl_p + 2ull * DIM * DIM, WN4);
    k_cvt<<<(WN4 + 255) / 256, 256>>>(Weq, wh_p + 3ull * DIM * DIM, wl_p + 3ull * DIM * DIM, WN4);
    k_cvt<<<(WN4 + 255) / 256, 256>>>(Wek, wh_p + 4ull * DIM * DIM, wl_p + 4ull * DIM * DIM, WN4);
    k_cvt<<<(WN4 + 255) / 256, 256>>>(Wo,  wh_p + 5ull * DIM * DIM, wl_p + 5ull * DIM * DIM, WN4);

    k_proj5<<<dim3(8, 16, 5), 256, GSMEM>>>(bq, bk, bv, beq, bek);
    k_ampph<<<2048, 256>>>(hs, aw, ab, pw, pb);
    k_mixed<<<dim3(64, 16), 256>>>(mw, mb);
    k_attn<<<dim3(32, 16), 256, ATTN_SMEM_BYTES>>>();

    k_cvt<<<(AN4 + 255) / 256, 256>>>(ctx_p, ah_p, al_p, AN4);
    k_wo<<<dim3(8, 16), 256, GSMEM>>>(bo, hs);
    k_ln<<<2048, 256>>>(lg, lb, out);
}

// round 7
// speedup vs baseline: 3.8635x; 2.7245x over previous
#include <cuda_runtime.h>
#include <cuda_bf16.h>

#define SEQ 2048
#define DIM 1024
#define NH 16
#define HDIM 64
#define SCALE 0.125f
#define ENTW 0.5f
#define DECAYC 0.1f
#define SUPW 0.3f
#define LNEPS 1e-5f
#define PI_F 3.14159265358979323846f

// ---------------- scratch ----------------
__device__ float g_v[SEQ * DIM];
__device__ float g_ctx[SEQ * DIM];
__device__ float g_res[SEQ * DIM];
__device__ float g_ca[SEQ * NH];
__device__ float g_sa[SEQ * NH];
__device__ __nv_bfloat16 g_qb[SEQ * DIM];
__device__ __nv_bfloat16 g_kb[SEQ * DIM];
__device__ __nv_bfloat16 g_eqb[SEQ * DIM];
__device__ __nv_bfloat16 g_ekb[SEQ * DIM];
__device__ __nv_bfloat16 g_ab[SEQ * DIM];          // activations (hs, then ctx)
__device__ __nv_bfloat16 g_wb[6 * DIM * DIM];      // weights bf16
__device__ __nv_bfloat16 g_mxT[DIM * SEQ];         // mixed, transposed [h*64+d][s]

// ---------------- helpers ----------------
__device__ __forceinline__ unsigned smem_u32(const void* p) {
    unsigned a;
    asm("{ .reg .u64 t; cvta.to.shared.u64 t, %1; cvt.u32.u64 %0, t; }" : "=r"(a) : "l"(p));
    return a;
}
__device__ __forceinline__ void cp16(unsigned d, const void* s) {
    asm volatile("cp.async.cg.shared.global [%0], [%1], 16;" :: "r"(d), "l"(s));
}
__device__ __forceinline__ void ldm4(unsigned* r, unsigned a) {
    asm volatile("ldmatrix.sync.aligned.m8n8.x4.shared.b16 {%0,%1,%2,%3}, [%4];"
        : "=r"(r[0]), "=r"(r[1]), "=r"(r[2]), "=r"(r[3]) : "r"(a));
}
__device__ __forceinline__ void mmabf(float* d, const unsigned* a, const unsigned* b) {
    asm volatile(
        "mma.sync.aligned.m16n8k16.row.col.f32.bf16.bf16.f32 "
        "{%0,%1,%2,%3}, {%4,%5,%6,%7}, {%8,%9}, {%0,%1,%2,%3};"
        : "+f"(d[0]), "+f"(d[1]), "+f"(d[2]), "+f"(d[3])
        : "r"(a[0]), "r"(a[1]), "r"(a[2]), "r"(a[3]), "r"(b[0]), "r"(b[1]));
}

// ---------------- fp32 -> bf16 conversion ----------------
__global__ __launch_bounds__(256) void k_cvt1(const float* __restrict__ s,
                                              __nv_bfloat16* __restrict__ o, int n4) {
    int i = blockIdx.x * 256 + threadIdx.x;
    if (i >= n4) return;
    float4 x = ((const float4*)s)[i];
    __nv_bfloat162 a, b;
    a.x = __float2bfloat16(x.x); a.y = __float2bfloat16(x.y);
    b.x = __float2bfloat16(x.z); b.y = __float2bfloat16(x.w);
    ((__nv_bfloat162*)o)[i * 2] = a;
    ((__nv_bfloat162*)o)[i * 2 + 1] = b;
}

// ---------------- single-bf16 mma GEMM: C = A @ W^T + bias (+resid) ----------------
#define RSTR 40
#define PLANE 10240             // 128*RSTR*2
#define STAGE (2 * PLANE)       // A, B planes
#define GSMEM (2 * STAGE)       // 40960 B

__device__ __forceinline__ void load_chunk(unsigned st,
        const __nv_bfloat16* __restrict__ A, const __nv_bfloat16* __restrict__ B,
        int m0, int n0, int k0, int tid) {
#pragma unroll
    for (int i = 0; i < 4; i++) {
        int idx = i * 256 + tid;           // 0..1023
        int plane = idx >> 9;              // 0..1
        int row = (idx >> 2) & 127;
        int ck = idx & 3;
        unsigned soff = st + plane * PLANE + (unsigned)(row * RSTR + ck * 8) * 2;
        const __nv_bfloat16* gp = plane
            ? (B + (size_t)(n0 + row) * DIM + k0 + ck * 8)
            : (A + (size_t)(m0 + row) * DIM + k0 + ck * 8);
        cp16(soff, gp);
    }
    asm volatile("cp.async.commit_group;" ::: "memory");
}

__device__ __forceinline__ void gemm_mma(
        const __nv_bfloat16* __restrict__ A, const __nv_bfloat16* __restrict__ W,
        const float* __restrict__ bias, const float* __restrict__ resid,
        float* __restrict__ Cf, __nv_bfloat16* __restrict__ Cb) {
    extern __shared__ char dynsm[];
    unsigned sb = smem_u32(dynsm);
    int tid = threadIdx.x, lane = tid & 31, w = tid >> 5;
    int wm = w & 1, wn = w >> 1;
    int m0 = blockIdx.y * 128, n0 = blockIdx.x * 128;

    float acc[4][4][4];
#pragma unroll
    for (int a = 0; a < 4; a++)
#pragma unroll
        for (int b = 0; b < 4; b++)
#pragma unroll
            for (int d = 0; d < 4; d++) acc[a][b][d] = 0.f;

    load_chunk(sb, A, W, m0, n0, 0, tid);

    int lrA = lane & 15;
    int lcA = (lane >> 4) << 3;
    int lnB = (lane & 7) + ((lane >> 4) << 3);
    int lkB = ((lane >> 3) & 1) << 3;
    unsigned aRow = (unsigned)((wm * 64 + lrA) * RSTR) * 2;
    unsigned bRow = (unsigned)((wn * 32 + lnB) * RSTR) * 2;

    for (int c = 0; c < 32; c++) {
        asm volatile("cp.async.wait_group 0;" ::: "memory");
        __syncthreads();
        if (c < 31)
            load_chunk(sb + ((c + 1) & 1) * STAGE, A, W, m0, n0, (c + 1) * 32, tid);
        unsigned st = sb + (c & 1) * STAGE;
#pragma unroll
        for (int ks = 0; ks < 32; ks += 16) {
            unsigned ah[4][4], bh[4][2];
#pragma unroll
            for (int mt = 0; mt < 4; mt++)
                ldm4(ah[mt], st + aRow + (unsigned)(mt * 16 * RSTR + ks + lcA) * 2);
#pragma unroll
            for (int p = 0; p < 2; p++) {
                unsigned t[4];
                ldm4(t, st + PLANE + bRow + (unsigned)(p * 16 * RSTR + ks + lkB) * 2);
                bh[2 * p][0] = t[0]; bh[2 * p][1] = t[1];
                bh[2 * p + 1][0] = t[2]; bh[2 * p + 1][1] = t[3];
            }
#pragma unroll
            for (int mt = 0; mt < 4; mt++)
#pragma unroll
                for (int nt = 0; nt < 4; nt++)
                    mmabf(acc[mt][nt], ah[mt], bh[nt]);
        }
        __syncthreads();
    }

    int r0 = m0 + wm * 64 + (lane >> 2);
    int cb = n0 + wn * 32 + (lane & 3) * 2;
#pragma unroll
    for (int mt = 0; mt < 4; mt++) {
#pragma unroll
        for (int nt = 0; nt < 4; nt++) {
            int rr = r0 + mt * 16;
            int cc = cb + nt * 8;
            float b0 = bias[cc], b1 = bias[cc + 1];
            float2 v0 = make_float2(acc[mt][nt][0] + b0, acc[mt][nt][1] + b1);
            float2 v1 = make_float2(acc[mt][nt][2] + b0, acc[mt][nt][3] + b1);
            if (resid) {
                const float2 q0 = *(const float2*)(resid + (size_t)rr * DIM + cc);
                const float2 q1 = *(const float2*)(resid + (size_t)(rr + 8) * DIM + cc);
                v0.x += q0.x; v0.y += q0.y;
                v1.x += q1.x; v1.y += q1.y;
            }
            if (Cb) {
                __nv_bfloat162 o0, o1;
                o0.x = __float2bfloat16(v0.x); o0.y = __float2bfloat16(v0.y);
                o1.x = __float2bfloat16(v1.x); o1.y = __float2bfloat16(v1.y);
                *(__nv_bfloat162*)(Cb + (size_t)rr * DIM + cc) = o0;
                *(__nv_bfloat162*)(Cb + (size_t)(rr + 8) * DIM + cc) = o1;
            } else {
                *(float2*)(Cf + (size_t)rr * DIM + cc) = v0;
                *(float2*)(Cf + (size_t)(rr + 8) * DIM + cc) = v1;
            }
        }
    }
}

__global__ __launch_bounds__(256) void k_proj5(
        const float* __restrict__ bq, const float* __restrict__ bk,
        const float* __restrict__ bv, const float* __restrict__ beq,
        const float* __restrict__ bek) {
    int z = blockIdx.z;
    const float* bias; float* Cf = nullptr; __nv_bfloat16* Cb = nullptr;
    switch (z) {
        case 0:  bias = bq;  Cb = g_qb;  break;
        case 1:  bias = bk;  Cb = g_kb;  break;
        case 2:  bias = bv;  Cf = g_v;   break;
        case 3:  bias = beq; Cb = g_eqb; break;
        default: bias = bek; Cb = g_ekb; break;
    }
    gemm_mma(g_ab, g_wb + (size_t)z * DIM * DIM, bias, nullptr, Cf, Cb);
}

__global__ __launch_bounds__(256) void k_wo(const float* __restrict__ bo,
                                            const float* __restrict__ hs) {
    gemm_mma(g_ab, g_wb + 5ull * DIM * DIM, bo, hs, g_res, nullptr);
}

// ---------------- K2: amplitudes & phases ----------------
__global__ __launch_bounds__(256) void k_ampph(const float* __restrict__ hs,
                                               const float* __restrict__ aw,
                                               const float* __restrict__ ab,
                                               const float* __restrict__ pw,
                                               const float* __restrict__ pb) {
    __shared__ float row[DIM];
    __shared__ float acc[32];
    int s = blockIdx.x, tid = threadIdx.x;
    for (int i = tid; i < DIM; i += 256) row[i] = hs[(size_t)s * DIM + i];
    __syncthreads();
    int w = tid >> 5, lane = tid & 31;
#pragma unroll
    for (int t = 0; t < 4; t++) {
        int o = w * 4 + t;
        int hh = o & 15;
        const float* wp = (o < 16) ? (aw + (size_t)hh * DIM) : (pw + (size_t)hh * DIM);
        float sum = 0.f;
        for (int i = lane; i < DIM; i += 32) sum += row[i] * wp[i];
#pragma unroll
        for (int m = 16; m; m >>= 1) sum += __shfl_xor_sync(0xffffffffu, sum, m);
        if (lane == 0) acc[o] = sum + ((o < 16) ? ab[hh] : pb[hh]);
    }
    __syncthreads();
    if (tid < NH) {
        float a = 1.f / (1.f + expf(-acc[tid]));
        float ph = tanhf(acc[16 + tid]) * PI_F;
        float sp, cp;
        sincosf(ph, &sp, &cp);
        g_ca[s * NH + tid] = SUPW * a * cp;
        g_sa[s * NH + tid] = SUPW * a * sp;
    }
}

// ---------------- K3: superposition mixer -> g_mxT (transposed bf16) ----------------
__global__ __launch_bounds__(256) void k_mixed(const float* __restrict__ mw_g,
                                               const float* __restrict__ mb_g) {
    __shared__ float mw[64][65];
    __shared__ float vt[32][65];
    __shared__ float sp[32][65];
    __shared__ float mb[64];
    int h = blockIdx.y, s0 = blockIdx.x * 32;
    int tid = threadIdx.x;
    for (int i = tid; i < 4096; i += 256) mw[i >> 6][i & 63] = mw_g[h * 4096 + i];
    if (tid < 64) mb[tid] = mb_g[h * 64 + tid];
    for (int i = tid; i < 2048; i += 256)
        vt[i >> 6][i & 63] = g_v[(size_t)(s0 + (i >> 6)) * DIM + h * HDIM + (i & 63)];
    __syncthreads();

    int r = tid >> 3;
    int ob = (tid & 7) * 8;
    float a[8];
#pragma unroll
    for (int j = 0; j < 8; j++) a[j] = 0.f;
    for (int d = 0; d < 64; d++) {
        float vv = vt[r][d];
#pragma unroll
        for (int j = 0; j < 8; j++) a[j] += vv * mw[ob + j][d];
    }
#pragma unroll
    for (int j = 0; j < 8; j++) sp[r][ob + j] = a[j] + mb[ob + j];
    __syncthreads();

    // write transposed: g_mxT[(h*64+d)*SEQ + s]
    for (int i = tid; i < 2048; i += 256) {
        int d = i >> 5, sl = i & 31;
        float ca = g_ca[(s0 + sl) * NH + h];
        float sa = g_sa[(s0 + sl) * NH + h];
        float val = vt[sl][d] + ca * sp[sl][d] + sa * sp[sl][(d + 63) & 63];
        g_mxT[(size_t)(h * HDIM + d) * SEQ + s0 + sl] = __float2bfloat16(val);
    }
}

// ---------------- K4: tensor-core flash attention ----------------
// smem offsets (bf16 tiles stride 72 elems = 144 B)
#define AO_Q 0
#define AO_E 9216
#define AO_K 18432
#define AO_F 27648
#define AO_M 36864
#define AO_P 46080
#define AO_S 55296
#define AO_D 72704
#define AO_A 73216
#define AO_L 73472
#define ATT_SMEM 73728

__global__ __launch_bounds__(256, 2) void k_attn_tc() {
    extern __shared__ __align__(16) char smc[];
    unsigned sb = smem_u32(smc);
    float* Sbuf = (float*)(smc + AO_S);
    float* dtab = (float*)(smc + AO_D);
    float* alph = (float*)(smc + AO_A);
    float* linv = (float*)(smc + AO_L);
    __nv_bfloat16* Pp = (__nv_bfloat16*)(smc + AO_P);

    int h = blockIdx.y, q0 = blockIdx.x * 64;
    int tid = threadIdx.x, lane = tid & 31, w = tid >> 5;
    int wm = w & 1, wn = w >> 1;
    int ty = tid >> 4, tx = tid & 15;
    size_t hoff = (size_t)h * HDIM;

    // load Q, EQ tiles (64 rows x 64 bf16, 8 chunks of 16B per row)
#pragma unroll
    for (int t = 0; t < 2; t++) {
        int idx = tid + t * 256;
        int row = idx >> 3, ck = idx & 7;
        cp16(sb + AO_Q + row * 144 + ck * 16, g_qb + (size_t)(q0 + row) * DIM + hoff + ck * 8);
        cp16(sb + AO_E + row * 144 + ck * 16, g_eqb + (size_t)(q0 + row) * DIM + hoff + ck * 8);
    }
    asm volatile("cp.async.commit_group;" ::: "memory");

    float m_i[4], l_i[4];
#pragma unroll
    for (int i = 0; i < 4; i++) { m_i[i] = -1e30f; l_i[i] = 0.f; }
    float O[2][2][4];
#pragma unroll
    for (int a = 0; a < 2; a++)
#pragma unroll
        for (int b = 0; b < 2; b++)
#pragma unroll
            for (int d = 0; d < 4; d++) O[a][b][d] = 0.f;

    // frag byte offsets within a tile (stride 144 B)
    unsigned aoff = (unsigned)((wm * 32 + (lane & 15)) * 144 + ((lane >> 4) << 4));
    unsigned boff = (unsigned)(((wn * 16) + (lane & 7) + ((lane >> 4) << 3)) * 144 +
                               (((lane >> 3) & 1) << 4));
    int fr = lane >> 2;            // frag row within 16
    int fc = (lane & 3) * 2;       // frag col pair

    for (int kt = 0; kt < 32; kt++) {
        int k0 = kt * 64;
        int dq = q0 - k0;
        int adq = dq < 0 ? -dq : dq;
        bool ent = (adq <= 384);

        __syncthreads();   // previous iteration consumers done
#pragma unroll
        for (int t = 0; t < 2; t++) {
            int idx = tid + t * 256;
            int row = idx >> 3, ck = idx & 7;
            cp16(sb + AO_K + row * 144 + ck * 16,
                 g_kb + (size_t)(k0 + row) * DIM + hoff + ck * 8);
            cp16(sb + AO_M + row * 144 + ck * 16,
                 g_mxT + (hoff + row) * SEQ + k0 + ck * 8);
            if (ent)
                cp16(sb + AO_F + row * 144 + ck * 16,
                     g_ekb + (size_t)(k0 + row) * DIM + hoff + ck * 8);
        }
        asm volatile("cp.async.commit_group;" ::: "memory");
        if (tid < 127)
            dtab[tid] = __expf(-DECAYC * fabsf((float)(dq + tid - 63)));
        asm volatile("cp.async.wait_group 0;" ::: "memory");
        __syncthreads();

        // --- scores via MMA ---
        float sacc[2][2][4], eacc[2][2][4];
#pragma unroll
        for (int a = 0; a < 2; a++)
#pragma unroll
            for (int b = 0; b < 2; b++)
#pragma unroll
                for (int d = 0; d < 4; d++) { sacc[a][b][d] = 0.f; eacc[a][b][d] = 0.f; }

#pragma unroll
        for (int ks = 0; ks < 4; ks++) {
            unsigned qa0[4], qa1[4], kb[4];
            ldm4(qa0, sb + AO_Q + aoff + ks * 32);
            ldm4(qa1, sb + AO_Q + aoff + 2304 + ks * 32);
            ldm4(kb, sb + AO_K + boff + ks * 32);
            mmabf(sacc[0][0], qa0, kb); mmabf(sacc[0][1], qa0, kb + 2);
            mmabf(sacc[1][0], qa1, kb); mmabf(sacc[1][1], qa1, kb + 2);
            if (ent) {
                ldm4(qa0, sb + AO_E + aoff + ks * 32);
                ldm4(qa1, sb + AO_E + aoff + 2304 + ks * 32);
                ldm4(kb, sb + AO_F + boff + ks * 32);
                mmabf(eacc[0][0], qa0, kb); mmabf(eacc[0][1], qa0, kb + 2);
                mmabf(eacc[1][0], qa1, kb); mmabf(eacc[1][1], qa1, kb + 2);
            }
        }

        // write scores to smem
#pragma unroll
        for (int mt = 0; mt < 2; mt++)
#pragma unroll
            for (int nt = 0; nt < 2; nt++) {
                int r = wm * 32 + mt * 16 + fr;
                int c = wn * 16 + nt * 8 + fc;
                float s0 = SCALE * sacc[mt][nt][0];
                float s1 = SCALE * sacc[mt][nt][1];
                float s2 = SCALE * sacc[mt][nt][2];
                float s3 = SCALE * sacc[mt][nt][3];
                if (ent) {
                    int b = r - c + 63;
                    s0 += (ENTW * SCALE) * dtab[b] * eacc[mt][nt][0];
                    s1 += (ENTW * SCALE) * dtab[b - 1] * eacc[mt][nt][1];
                    s2 += (ENTW * SCALE) * dtab[b + 8] * eacc[mt][nt][2];
                    s3 += (ENTW * SCALE) * dtab[b + 7] * eacc[mt][nt][3];
                }
                *(float2*)&Sbuf[r * 68 + c] = make_float2(s0, s1);
                *(float2*)&Sbuf[(r + 8) * 68 + c] = make_float2(s2, s3);
            }
        __syncthreads();

        // --- online softmax (threads ty,tx own rows ty*4+i) ---
#pragma unroll
        for (int i = 0; i < 4; i++) {
            int rr = ty * 4 + i;
            float sv[4];
            float mx = -1e30f;
#pragma unroll
            for (int j = 0; j < 4; j++) {
                sv[j] = Sbuf[rr * 68 + tx + 16 * j];
                mx = fmaxf(mx, sv[j]);
            }
#pragma unroll
            for (int o = 1; o < 16; o <<= 1)
                mx = fmaxf(mx, __shfl_xor_sync(0xffffffffu, mx, o));
            float mnew = fmaxf(m_i[i], mx);
            float alpha = __expf(m_i[i] - mnew);
            float sum = 0.f;
#pragma unroll
            for (int j = 0; j < 4; j++) {
                float p = __expf(sv[j] - mnew);
                Pp[rr * 72 + tx + 16 * j] = __float2bfloat16(p);
                sum += p;
            }
#pragma unroll
            for (int o = 1; o < 16; o <<= 1)
                sum += __shfl_xor_sync(0xffffffffu, sum, o);
            l_i[i] = l_i[i] * alpha + sum;
            m_i[i] = mnew;
            if (tx == 0) alph[rr] = alpha;
        }
        __syncthreads();

        // --- scale O, then O += P @ MixedT ---
#pragma unroll
        for (int mt = 0; mt < 2; mt++) {
            float a0 = alph[wm * 32 + mt * 16 + fr];
            float a1 = alph[wm * 32 + mt * 16 + fr + 8];
#pragma unroll
            for (int nt = 0; nt < 2; nt++) {
                O[mt][nt][0] *= a0; O[mt][nt][1] *= a0;
                O[mt][nt][2] *= a1; O[mt][nt][3] *= a1;
            }
        }
#pragma unroll
        for (int ks = 0; ks < 4; ks++) {
            unsigned pa0[4], pa1[4], mb[4];
            ldm4(pa0, sb + AO_P + aoff + ks * 32);
            ldm4(pa1, sb + AO_P + aoff + 2304 + ks * 32);
            ldm4(mb, sb + AO_M + boff + ks * 32);
            mmabf(O[0][0], pa0, mb); mmabf(O[0][1], pa0, mb + 2);
            mmabf(O[1][0], pa1, mb); mmabf(O[1][1], pa1, mb + 2);
        }
    }

    // finalize
#pragma unroll
    for (int i = 0; i < 4; i++)
        if (tx == 0) linv[ty * 4 + i] = 1.f / l_i[i];
    __syncthreads();
#pragma unroll
    for (int mt = 0; mt < 2; mt++)
#pragma unroll
        for (int nt = 0; nt < 2; nt++) {
            int r = wm * 32 + mt * 16 + fr;
            int c = wn * 16 + nt * 8 + fc;
            float i0 = linv[r], i1 = linv[r + 8];
            *(float2*)&g_ctx[(size_t)(q0 + r) * DIM + hoff + c] =
                make_float2(O[mt][nt][0] * i0, O[mt][nt][1] * i0);
            *(float2*)&g_ctx[(size_t)(q0 + r + 8) * DIM + hoff + c] =
                make_float2(O[mt][nt][2] * i1, O[mt][nt][3] * i1);
        }
}

// ---------------- K6: LayerNorm ----------------
__global__ __launch_bounds__(256) void k_ln(const float* __restrict__ g,
                                            const float* __restrict__ b,
                                            float* __restrict__ out) {
    __shared__ float s1[8], s2[8], mv[2];
    int s = blockIdx.x, tid = threadIdx.x;
    const float* r = g_res + (size_t)s * DIM;
    float4 x = *(const float4*)(r + tid * 4);
    float sum = x.x + x.y + x.z + x.w;
    float sq = x.x * x.x + x.y * x.y + x.z * x.z + x.w * x.w;
#pragma unroll
    for (int o = 16; o; o >>= 1) {
        sum += __shfl_xor_sync(0xffffffffu, sum, o);
        sq  += __shfl_xor_sync(0xffffffffu, sq, o);
    }
    if ((tid & 31) == 0) { s1[tid >> 5] = sum; s2[tid >> 5] = sq; }
    __syncthreads();
    if (tid == 0) {
        float a = 0.f, c = 0.f;
#pragma unroll
        for (int i = 0; i < 8; i++) { a += s1[i]; c += s2[i]; }
        float mean = a * (1.f / DIM);
        float var = c * (1.f / DIM) - mean * mean;
        mv[0] = mean;
        mv[1] = rsqrtf(var + LNEPS);
    }
    __syncthreads();
    float mean = mv[0], rs = mv[1];
    int c0 = tid * 4;
    float4 gg = *(const float4*)(g + c0);
    float4 bb = *(const float4*)(b + c0);
    float4 o;
    o.x = (x.x - mean) * rs * gg.x + bb.x;
    o.y = (x.y - mean) * rs * gg.y + bb.y;
    o.z = (x.z - mean) * rs * gg.z + bb.z;
    o.w = (x.w - mean) * rs * gg.w + bb.w;
    *(float4*)(out + (size_t)s * DIM + c0) = o;
}

// ---------------- launch ----------------
extern "C" void kernel_launch(void* const* d_in, const int* in_sizes, int n_in,
                              void* d_out, int out_size) {
    const float* hs  = (const float*)d_in[0];
    const float* Wq  = (const float*)d_in[1];  const float* bq  = (const float*)d_in[2];
    const float* Wk  = (const float*)d_in[3];  const float* bk  = (const float*)d_in[4];
    const float* Wv  = (const float*)d_in[5];  const float* bv  = (const float*)d_in[6];
    const float* Wo  = (const float*)d_in[7];  const float* bo  = (const float*)d_in[8];
    const float* Weq = (const float*)d_in[9];  const float* beq = (const float*)d_in[10];
    const float* Wek = (const float*)d_in[11]; const float* bek = (const float*)d_in[12];
    const float* aw  = (const float*)d_in[13]; const float* ab  = (const float*)d_in[14];
    const float* pw  = (const float*)d_in[15]; const float* pb  = (const float*)d_in[16];
    const float* mw  = (const float*)d_in[17]; const float* mb  = (const float*)d_in[18];
    const float* lg  = (const float*)d_in[19]; const float* lb  = (const float*)d_in[20];
    float* out = (float*)d_out;

    static __nv_bfloat16* wb_p = nullptr;
    static __nv_bfloat16* ab_p = nullptr;
    static float* ctx_p = nullptr;
    if (!wb_p) {
        cudaGetSymbolAddress((void**)&wb_p, g_wb);
        cudaGetSymbolAddress((void**)&ab_p, g_ab);
        cudaGetSymbolAddress((void**)&ctx_p, g_ctx);
        cudaFuncSetAttribute(k_attn_tc, cudaFuncAttributeMaxDynamicSharedMemorySize,
                             ATT_SMEM);
    }

    const int WN4 = DIM * DIM / 4;     // 262144
    const int AN4 = SEQ * DIM / 4;     // 524288

    k_cvt1<<<(AN4 + 255) / 256, 256>>>(hs, ab_p, AN4);
    k_cvt1<<<(WN4 + 255) / 256, 256>>>(Wq,  wb_p + 0ull * DIM * DIM, WN4);
    k_cvt1<<<(WN4 + 255) / 256, 256>>>(Wk,  wb_p + 1ull * DIM * DIM, WN4);
    k_cvt1<<<(WN4 + 255) / 256, 256>>>(Wv,  wb_p + 2ull * DIM * DIM, WN4);
    k_cvt1<<<(WN4 + 255) / 256, 256>>>(Weq, wb_p + 3ull * DIM * DIM, WN4);
    k_cvt1<<<(WN4 + 255) / 256, 256>>>(Wek, wb_p + 4ull * DIM * DIM, WN4);
    k_cvt1<<<(WN4 + 255) / 256, 256>>>(Wo,  wb_p + 5ull * DIM * DIM, WN4);

    k_proj5<<<dim3(8, 16, 5), 256, GSMEM>>>(bq, bk, bv, beq, bek);
    k_ampph<<<2048, 256>>>(hs, aw, ab, pw, pb);
    k_mixed<<<dim3(64, 16), 256>>>(mw, mb);
    k_attn_tc<<<dim3(32, 16), 256, ATT_SMEM>>>();

    k_cvt1<<<(AN4 + 255) / 256, 256>>>(ctx_p, ab_p, AN4);
    k_wo<<<dim3(8, 16), 256, GSMEM>>>(bo, hs);
    k_ln<<<2048, 256>>>(lg, lb, out);
}

// round 8
// speedup vs baseline: 4.0831x; 1.0568x over previous
#include <cuda_runtime.h>
#include <cuda_bf16.h>

#define SEQ 2048
#define DIM 1024
#define NH 16
#define HDIM 64
#define SCALE 0.125f
#define ENTW 0.5f
#define DECAYC 0.1f
#define SUPW 0.3f
#define LNEPS 1e-5f
#define PI_F 3.14159265358979323846f

// ---------------- scratch ----------------
__device__ float g_v[SEQ * DIM];
__device__ float g_res[SEQ * DIM];
__device__ float g_ca[SEQ * NH];
__device__ float g_sa[SEQ * NH];
__device__ __nv_bfloat16 g_qb[SEQ * DIM];
__device__ __nv_bfloat16 g_kb[SEQ * DIM];
__device__ __nv_bfloat16 g_eqb[SEQ * DIM];
__device__ __nv_bfloat16 g_ekb[SEQ * DIM];
__device__ __nv_bfloat16 g_ab[SEQ * DIM];          // activations (hs, then ctx)
__device__ __nv_bfloat16 g_wb[6 * DIM * DIM];      // weights bf16
__device__ __nv_bfloat16 g_mxT[DIM * SEQ];         // mixed, transposed [h*64+d][s]

// ---------------- helpers ----------------
__device__ __forceinline__ unsigned smem_u32(const void* p) {
    unsigned a;
    asm("{ .reg .u64 t; cvta.to.shared.u64 t, %1; cvt.u32.u64 %0, t; }" : "=r"(a) : "l"(p));
    return a;
}
__device__ __forceinline__ void cp16(unsigned d, const void* s) {
    asm volatile("cp.async.cg.shared.global [%0], [%1], 16;" :: "r"(d), "l"(s));
}
__device__ __forceinline__ void ldm4(unsigned* r, unsigned a) {
    asm volatile("ldmatrix.sync.aligned.m8n8.x4.shared.b16 {%0,%1,%2,%3}, [%4];"
        : "=r"(r[0]), "=r"(r[1]), "=r"(r[2]), "=r"(r[3]) : "r"(a));
}
__device__ __forceinline__ void mmabf(float* d, const unsigned* a, const unsigned* b) {
    asm volatile(
        "mma.sync.aligned.m16n8k16.row.col.f32.bf16.bf16.f32 "
        "{%0,%1,%2,%3}, {%4,%5,%6,%7}, {%8,%9}, {%0,%1,%2,%3};"
        : "+f"(d[0]), "+f"(d[1]), "+f"(d[2]), "+f"(d[3])
        : "r"(a[0]), "r"(a[1]), "r"(a[2]), "r"(a[3]), "r"(b[0]), "r"(b[1]));
}

// ---------------- fp32 -> bf16 conversions ----------------
__global__ __launch_bounds__(256) void k_cvt1(const float* __restrict__ s,
                                              __nv_bfloat16* __restrict__ o, int n4) {
    int i = blockIdx.x * 256 + threadIdx.x;
    if (i >= n4) return;
    float4 x = ((const float4*)s)[i];
    __nv_bfloat162 a, b;
    a.x = __float2bfloat16(x.x); a.y = __float2bfloat16(x.y);
    b.x = __float2bfloat16(x.z); b.y = __float2bfloat16(x.w);
    ((__nv_bfloat162*)o)[i * 2] = a;
    ((__nv_bfloat162*)o)[i * 2 + 1] = b;
}

// all 6 weights in one launch; grid (1024, 6)
__global__ __launch_bounds__(256) void k_cvtw(
        const float* __restrict__ w0, const float* __restrict__ w1,
        const float* __restrict__ w2, const float* __restrict__ w3,
        const float* __restrict__ w4, const float* __restrict__ w5,
        __nv_bfloat16* __restrict__ o) {
    const float* src;
    switch (blockIdx.y) {
        case 0: src = w0; break;
        case 1: src = w1; break;
        case 2: src = w2; break;
        case 3: src = w3; break;
        case 4: src = w4; break;
        default: src = w5; break;
    }
    int i = blockIdx.x * 256 + threadIdx.x;       // < 262144
    float4 x = ((const float4*)src)[i];
    __nv_bfloat16* op = o + (size_t)blockIdx.y * DIM * DIM;
    __nv_bfloat162 a, b;
    a.x = __float2bfloat16(x.x); a.y = __float2bfloat16(x.y);
    b.x = __float2bfloat16(x.z); b.y = __float2bfloat16(x.w);
    ((__nv_bfloat162*)op)[i * 2] = a;
    ((__nv_bfloat162*)op)[i * 2 + 1] = b;
}

// ---------------- single-bf16 mma GEMM: C = A @ W^T + bias (+resid) ----------------
#define RSTR 40
#define PLANE 10240             // 128*RSTR*2
#define STAGE (2 * PLANE)       // A, B planes
#define GSMEM (2 * STAGE)       // 40960 B

__device__ __forceinline__ void load_chunk(unsigned st,
        const __nv_bfloat16* __restrict__ A, const __nv_bfloat16* __restrict__ B,
        int m0, int n0, int k0, int tid) {
#pragma unroll
    for (int i = 0; i < 4; i++) {
        int idx = i * 256 + tid;
        int plane = idx >> 9;
        int row = (idx >> 2) & 127;
        int ck = idx & 3;
        unsigned soff = st + plane * PLANE + (unsigned)(row * RSTR + ck * 8) * 2;
        const __nv_bfloat16* gp = plane
            ? (B + (size_t)(n0 + row) * DIM + k0 + ck * 8)
            : (A + (size_t)(m0 + row) * DIM + k0 + ck * 8);
        cp16(soff, gp);
    }
    asm volatile("cp.async.commit_group;" ::: "memory");
}

__device__ __forceinline__ void gemm_mma(
        const __nv_bfloat16* __restrict__ A, const __nv_bfloat16* __restrict__ W,
        const float* __restrict__ bias, const float* __restrict__ resid,
        float* __restrict__ Cf, __nv_bfloat16* __restrict__ Cb) {
    extern __shared__ char dynsm[];
    unsigned sb = smem_u32(dynsm);
    int tid = threadIdx.x, lane = tid & 31, w = tid >> 5;
    int wm = w & 1, wn = w >> 1;
    int m0 = blockIdx.y * 128, n0 = blockIdx.x * 128;

    float acc[4][4][4];
#pragma unroll
    for (int a = 0; a < 4; a++)
#pragma unroll
        for (int b = 0; b < 4; b++)
#pragma unroll
            for (int d = 0; d < 4; d++) acc[a][b][d] = 0.f;

    load_chunk(sb, A, W, m0, n0, 0, tid);

    int lrA = lane & 15;
    int lcA = (lane >> 4) << 3;
    int lnB = (lane & 7) + ((lane >> 4) << 3);
    int lkB = ((lane >> 3) & 1) << 3;
    unsigned aRow = (unsigned)((wm * 64 + lrA) * RSTR) * 2;
    unsigned bRow = (unsigned)((wn * 32 + lnB) * RSTR) * 2;

    for (int c = 0; c < 32; c++) {
        asm volatile("cp.async.wait_group 0;" ::: "memory");
        __syncthreads();
        if (c < 31)
            load_chunk(sb + ((c + 1) & 1) * STAGE, A, W, m0, n0, (c + 1) * 32, tid);
        unsigned st = sb + (c & 1) * STAGE;
#pragma unroll
        for (int ks = 0; ks < 32; ks += 16) {
            unsigned ah[4][4], bh[4][2];
#pragma unroll
            for (int mt = 0; mt < 4; mt++)
                ldm4(ah[mt], st + aRow + (unsigned)(mt * 16 * RSTR + ks + lcA) * 2);
#pragma unroll
            for (int p = 0; p < 2; p++) {
                unsigned t[4];
                ldm4(t, st + PLANE + bRow + (unsigned)(p * 16 * RSTR + ks + lkB) * 2);
                bh[2 * p][0] = t[0]; bh[2 * p][1] = t[1];
                bh[2 * p + 1][0] = t[2]; bh[2 * p + 1][1] = t[3];
            }
#pragma unroll
            for (int mt = 0; mt < 4; mt++)
#pragma unroll
                for (int nt = 0; nt < 4; nt++)
                    mmabf(acc[mt][nt], ah[mt], bh[nt]);
        }
        __syncthreads();
    }

    int r0 = m0 + wm * 64 + (lane >> 2);
    int cb = n0 + wn * 32 + (lane & 3) * 2;
#pragma unroll
    for (int mt = 0; mt < 4; mt++) {
#pragma unroll
        for (int nt = 0; nt < 4; nt++) {
            int rr = r0 + mt * 16;
            int cc = cb + nt * 8;
            float b0 = bias[cc], b1 = bias[cc + 1];
            float2 v0 = make_float2(acc[mt][nt][0] + b0, acc[mt][nt][1] + b1);
            float2 v1 = make_float2(acc[mt][nt][2] + b0, acc[mt][nt][3] + b1);
            if (resid) {
                const float2 q0 = *(const float2*)(resid + (size_t)rr * DIM + cc);
                const float2 q1 = *(const float2*)(resid + (size_t)(rr + 8) * DIM + cc);
                v0.x += q0.x; v0.y += q0.y;
                v1.x += q1.x; v1.y += q1.y;
            }
            if (Cb) {
                __nv_bfloat162 o0, o1;
                o0.x = __float2bfloat16(v0.x); o0.y = __float2bfloat16(v0.y);
                o1.x = __float2bfloat16(v1.x); o1.y = __float2bfloat16(v1.y);
                *(__nv_bfloat162*)(Cb + (size_t)rr * DIM + cc) = o0;
                *(__nv_bfloat162*)(Cb + (size_t)(rr + 8) * DIM + cc) = o1;
            } else {
                *(float2*)(Cf + (size_t)rr * DIM + cc) = v0;
                *(float2*)(Cf + (size_t)(rr + 8) * DIM + cc) = v1;
            }
        }
    }
}

__global__ __launch_bounds__(256) void k_proj5(
        const float* __restrict__ bq, const float* __restrict__ bk,
        const float* __restrict__ bv, const float* __restrict__ beq,
        const float* __restrict__ bek) {
    int z = blockIdx.z;
    const float* bias; float* Cf = nullptr; __nv_bfloat16* Cb = nullptr;
    switch (z) {
        case 0:  bias = bq;  Cb = g_qb;  break;
        case 1:  bias = bk;  Cb = g_kb;  break;
        case 2:  bias = bv;  Cf = g_v;   break;
        case 3:  bias = beq; Cb = g_eqb; break;
        default: bias = bek; Cb = g_ekb; break;
    }
    gemm_mma(g_ab, g_wb + (size_t)z * DIM * DIM, bias, nullptr, Cf, Cb);
}

__global__ __launch_bounds__(256) void k_wo(const float* __restrict__ bo,
                                            const float* __restrict__ hs) {
    gemm_mma(g_ab, g_wb + 5ull * DIM * DIM, bo, hs, g_res, nullptr);
}

// ---------------- K2: amplitudes & phases ----------------
__global__ __launch_bounds__(256) void k_ampph(const float* __restrict__ hs,
                                               const float* __restrict__ aw,
                                               const float* __restrict__ ab,
                                               const float* __restrict__ pw,
                                               const float* __restrict__ pb) {
    __shared__ float row[DIM];
    __shared__ float acc[32];
    int s = blockIdx.x, tid = threadIdx.x;
    for (int i = tid; i < DIM; i += 256) row[i] = hs[(size_t)s * DIM + i];
    __syncthreads();
    int w = tid >> 5, lane = tid & 31;
#pragma unroll
    for (int t = 0; t < 4; t++) {
        int o = w * 4 + t;
        int hh = o & 15;
        const float* wp = (o < 16) ? (aw + (size_t)hh * DIM) : (pw + (size_t)hh * DIM);
        float sum = 0.f;
        for (int i = lane; i < DIM; i += 32) sum += row[i] * wp[i];
#pragma unroll
        for (int m = 16; m; m >>= 1) sum += __shfl_xor_sync(0xffffffffu, sum, m);
        if (lane == 0) acc[o] = sum + ((o < 16) ? ab[hh] : pb[hh]);
    }
    __syncthreads();
    if (tid < NH) {
        float a = 1.f / (1.f + expf(-acc[tid]));
        float ph = tanhf(acc[16 + tid]) * PI_F;
        float sp, cp;
        sincosf(ph, &sp, &cp);
        g_ca[s * NH + tid] = SUPW * a * cp;
        g_sa[s * NH + tid] = SUPW * a * sp;
    }
}

// ---------------- K3: superposition mixer -> g_mxT (transposed bf16) ----------------
__global__ __launch_bounds__(256) void k_mixed(const float* __restrict__ mw_g,
                                               const float* __restrict__ mb_g) {
    __shared__ float mw[64][65];
    __shared__ float vt[32][65];
    __shared__ float sp[32][65];
    __shared__ float mb[64];
    int h = blockIdx.y, s0 = blockIdx.x * 32;
    int tid = threadIdx.x;
    for (int i = tid; i < 4096; i += 256) mw[i >> 6][i & 63] = mw_g[h * 4096 + i];
    if (tid < 64) mb[tid] = mb_g[h * 64 + tid];
    for (int i = tid; i < 2048; i += 256)
        vt[i >> 6][i & 63] = g_v[(size_t)(s0 + (i >> 6)) * DIM + h * HDIM + (i & 63)];
    __syncthreads();

    int r = tid >> 3;
    int ob = (tid & 7) * 8;
    float a[8];
#pragma unroll
    for (int j = 0; j < 8; j++) a[j] = 0.f;
    for (int d = 0; d < 64; d++) {
        float vv = vt[r][d];
#pragma unroll
        for (int j = 0; j < 8; j++) a[j] += vv * mw[ob + j][d];
    }
#pragma unroll
    for (int j = 0; j < 8; j++) sp[r][ob + j] = a[j] + mb[ob + j];
    __syncthreads();

    for (int i = tid; i < 2048; i += 256) {
        int d = i >> 5, sl = i & 31;
        float ca = g_ca[(s0 + sl) * NH + h];
        float sa = g_sa[(s0 + sl) * NH + h];
        float val = vt[sl][d] + ca * sp[sl][d] + sa * sp[sl][(d + 63) & 63];
        g_mxT[(size_t)(h * HDIM + d) * SEQ + s0 + sl] = __float2bfloat16(val);
    }
}

// ---------------- K4: tensor-core flash attention (double-buffered) ----------------
#define AO_Q 0
#define AO_E 9216
#define AO_P 18432
#define AO_S 27648      // fp32 64*68
#define AO_D 45056      // dtab 128 f
#define AO_A 45568      // alpha 64 f
#define AO_L 45824      // linv 64 f
#define AO_ST 46080
#define STG_K 0
#define STG_M 9216
#define STG_F 18432
#define STG_SZ 27648
#define ATT_SMEM (AO_ST + 2 * STG_SZ)   // 101376

__device__ __forceinline__ void att_load(unsigned sb, int kt, int q0,
                                         size_t hoff, int tid) {
    int k0 = kt * 64;
    int dq = q0 - k0; int adq = dq < 0 ? -dq : dq;
    bool ent = (adq <= 384);
    unsigned st = sb + AO_ST + (kt & 1) * STG_SZ;
#pragma unroll
    for (int t = 0; t < 2; t++) {
        int idx = tid + t * 256;
        int row = idx >> 3, ck = idx & 7;
        cp16(st + STG_K + row * 144 + ck * 16,
             g_kb + (size_t)(k0 + row) * DIM + hoff + ck * 8);
        cp16(st + STG_M + row * 144 + ck * 16,
             g_mxT + (hoff + row) * SEQ + k0 + ck * 8);
        if (ent)
            cp16(st + STG_F + row * 144 + ck * 16,
                 g_ekb + (size_t)(k0 + row) * DIM + hoff + ck * 8);
    }
    asm volatile("cp.async.commit_group;" ::: "memory");
}

__global__ __launch_bounds__(256, 2) void k_attn_tc() {
    extern __shared__ __align__(16) char smc[];
    unsigned sb = smem_u32(smc);
    float* Sbuf = (float*)(smc + AO_S);
    float* dtab = (float*)(smc + AO_D);
    float* alph = (float*)(smc + AO_A);
    float* linv = (float*)(smc + AO_L);

    int h = blockIdx.y, q0 = blockIdx.x * 64;
    int tid = threadIdx.x, lane = tid & 31, w = tid >> 5;
    int wm = w & 1, wn = w >> 1;
    int ty = tid >> 4, tx = tid & 15;
    size_t hoff = (size_t)h * HDIM;

    // prologue: Q/EQ (group), then stage-0 K/M/F (group)
#pragma unroll
    for (int t = 0; t < 2; t++) {
        int idx = tid + t * 256;
        int row = idx >> 3, ck = idx & 7;
        cp16(sb + AO_Q + row * 144 + ck * 16,
             g_qb + (size_t)(q0 + row) * DIM + hoff + ck * 8);
        cp16(sb + AO_E + row * 144 + ck * 16,
             g_eqb + (size_t)(q0 + row) * DIM + hoff + ck * 8);
    }
    asm volatile("cp.async.commit_group;" ::: "memory");
    att_load(sb, 0, q0, hoff, tid);

    float m_i[4], l_i[4];
#pragma unroll
    for (int i = 0; i < 4; i++) { m_i[i] = -1e30f; l_i[i] = 0.f; }
    float O[2][2][4];
#pragma unroll
    for (int a = 0; a < 2; a++)
#pragma unroll
        for (int b = 0; b < 2; b++)
#pragma unroll
            for (int d = 0; d < 4; d++) O[a][b][d] = 0.f;

    unsigned aoff = (unsigned)((wm * 32 + (lane & 15)) * 144 + ((lane >> 4) << 4));
    unsigned boff = (unsigned)(((wn * 16) + (lane & 7) + ((lane >> 4) << 3)) * 144 +
                               (((lane >> 3) & 1) << 4));
    int fr = lane >> 2;
    int fc = (lane & 3) * 2;

    for (int kt = 0; kt < 32; kt++) {
        int k0 = kt * 64;
        int dq = q0 - k0;
        int adq = dq < 0 ? -dq : dq;
        bool ent = (adq <= 384);
        unsigned stb = sb + AO_ST + (kt & 1) * STG_SZ;

        __syncthreads();                 // stage (kt+1)&1 free (kt-1 consumers done)
        if (kt < 31) att_load(sb, kt + 1, q0, hoff, tid);
        if (tid < 127)
            dtab[tid] = __expf(-DECAYC * fabsf((float)(dq + tid - 63)));
        if (kt < 31) asm volatile("cp.async.wait_group 1;" ::: "memory");
        else         asm volatile("cp.async.wait_group 0;" ::: "memory");
        __syncthreads();

        // --- scores via MMA ---
        float sacc[2][2][4], eacc[2][2][4];
#pragma unroll
        for (int a = 0; a < 2; a++)
#pragma unroll
            for (int b = 0; b < 2; b++)
#pragma unroll
                for (int d = 0; d < 4; d++) { sacc[a][b][d] = 0.f; eacc[a][b][d] = 0.f; }

#pragma unroll
        for (int ks = 0; ks < 4; ks++) {
            unsigned qa0[4], qa1[4], kb[4];
            ldm4(qa0, sb + AO_Q + aoff + ks * 32);
            ldm4(qa1, sb + AO_Q + aoff + 2304 + ks * 32);
            ldm4(kb, stb + STG_K + boff + ks * 32);
            mmabf(sacc[0][0], qa0, kb); mmabf(sacc[0][1], qa0, kb + 2);
            mmabf(sacc[1][0], qa1, kb); mmabf(sacc[1][1], qa1, kb + 2);
            if (ent) {
                ldm4(qa0, sb + AO_E + aoff + ks * 32);
                ldm4(qa1, sb + AO_E + aoff + 2304 + ks * 32);
                ldm4(kb, stb + STG_F + boff + ks * 32);
                mmabf(eacc[0][0], qa0, kb); mmabf(eacc[0][1], qa0, kb + 2);
                mmabf(eacc[1][0], qa1, kb); mmabf(eacc[1][1], qa1, kb + 2);
            }
        }

#pragma unroll
        for (int mt = 0; mt < 2; mt++)
#pragma unroll
            for (int nt = 0; nt < 2; nt++) {
                int r = wm * 32 + mt * 16 + fr;
                int c = wn * 16 + nt * 8 + fc;
                float s0 = SCALE * sacc[mt][nt][0];
                float s1 = SCALE * sacc[mt][nt][1];
                float s2 = SCALE * sacc[mt][nt][2];
                float s3 = SCALE * sacc[mt][nt][3];
                if (ent) {
                    int b = r - c + 63;
                    s0 += (ENTW * SCALE) * dtab[b] * eacc[mt][nt][0];
                    s1 += (ENTW * SCALE) * dtab[b - 1] * eacc[mt][nt][1];
                    s2 += (ENTW * SCALE) * dtab[b + 8] * eacc[mt][nt][2];
                    s3 += (ENTW * SCALE) * dtab[b + 7] * eacc[mt][nt][3];
                }
                *(float2*)&Sbuf[r * 68 + c] = make_float2(s0, s1);
                *(float2*)&Sbuf[(r + 8) * 68 + c] = make_float2(s2, s3);
            }
        __syncthreads();

        // --- online softmax ---
        __nv_bfloat16* Pp = (__nv_bfloat16*)(smc + AO_P);
#pragma unroll
        for (int i = 0; i < 4; i++) {
            int rr = ty * 4 + i;
            float sv[4];
            float mx = -1e30f;
#pragma unroll
            for (int j = 0; j < 4; j++) {
                sv[j] = Sbuf[rr * 68 + tx + 16 * j];
                mx = fmaxf(mx, sv[j]);
            }
#pragma unroll
            for (int o = 1; o < 16; o <<= 1)
                mx = fmaxf(mx, __shfl_xor_sync(0xffffffffu, mx, o));
            float mnew = fmaxf(m_i[i], mx);
            float alpha = __expf(m_i[i] - mnew);
            float sum = 0.f;
#pragma unroll
            for (int j = 0; j < 4; j++) {
                float p = __expf(sv[j] - mnew);
                Pp[rr * 72 + tx + 16 * j] = __float2bfloat16(p);
                sum += p;
            }
#pragma unroll
            for (int o = 1; o < 16; o <<= 1)
                sum += __shfl_xor_sync(0xffffffffu, sum, o);
            l_i[i] = l_i[i] * alpha + sum;
            m_i[i] = mnew;
            if (tx == 0) alph[rr] = alpha;
        }
        __syncthreads();

        // --- scale O, then O += P @ MixedT ---
#pragma unroll
        for (int mt = 0; mt < 2; mt++) {
            float a0 = alph[wm * 32 + mt * 16 + fr];
            float a1 = alph[wm * 32 + mt * 16 + fr + 8];
#pragma unroll
            for (int nt = 0; nt < 2; nt++) {
                O[mt][nt][0] *= a0; O[mt][nt][1] *= a0;
                O[mt][nt][2] *= a1; O[mt][nt][3] *= a1;
            }
        }
#pragma unroll
        for (int ks = 0; ks < 4; ks++) {
            unsigned pa0[4], pa1[4], mb[4];
            ldm4(pa0, sb + AO_P + aoff + ks * 32);
            ldm4(pa1, sb + AO_P + aoff + 2304 + ks * 32);
            ldm4(mb, stb + STG_M + boff + ks * 32);
            mmabf(O[0][0], pa0, mb); mmabf(O[0][1], pa0, mb + 2);
            mmabf(O[1][0], pa1, mb); mmabf(O[1][1], pa1, mb + 2);
        }
    }

    // finalize -> write bf16 ctx directly into g_ab (A operand of Wo GEMM)
#pragma unroll
    for (int i = 0; i < 4; i++)
        if (tx == 0) linv[ty * 4 + i] = 1.f / l_i[i];
    __syncthreads();
#pragma unroll
    for (int mt = 0; mt < 2; mt++)
#pragma unroll
        for (int nt = 0; nt < 2; nt++) {
            int r = wm * 32 + mt * 16 + fr;
            int c = wn * 16 + nt * 8 + fc;
            float i0 = linv[r], i1 = linv[r + 8];
            __nv_bfloat162 o0, o1;
            o0.x = __float2bfloat16(O[mt][nt][0] * i0);
            o0.y = __float2bfloat16(O[mt][nt][1] * i0);
            o1.x = __float2bfloat16(O[mt][nt][2] * i1);
            o1.y = __float2bfloat16(O[mt][nt][3] * i1);
            *(__nv_bfloat162*)(g_ab + (size_t)(q0 + r) * DIM + hoff + c) = o0;
            *(__nv_bfloat162*)(g_ab + (size_t)(q0 + r + 8) * DIM + hoff + c) = o1;
        }
}

// ---------------- K6: LayerNorm ----------------
__global__ __launch_bounds__(256) void k_ln(const float* __restrict__ g,
                                            const float* __restrict__ b,
                                            float* __restrict__ out) {
    __shared__ float s1[8], s2[8], mv[2];
    int s = blockIdx.x, tid = threadIdx.x;
    const float* r = g_res + (size_t)s * DIM;
    float4 x = *(const float4*)(r + tid * 4);
    float sum = x.x + x.y + x.z + x.w;
    float sq = x.x * x.x + x.y * x.y + x.z * x.z + x.w * x.w;
#pragma unroll
    for (int o = 16; o; o >>= 1) {
        sum += __shfl_xor_sync(0xffffffffu, sum, o);
        sq  += __shfl_xor_sync(0xffffffffu, sq, o);
    }
    if ((tid & 31) == 0) { s1[tid >> 5] = sum; s2[tid >> 5] = sq; }
    __syncthreads();
    if (tid == 0) {
        float a = 0.f, c = 0.f;
#pragma unroll
        for (int i = 0; i < 8; i++) { a += s1[i]; c += s2[i]; }
        float mean = a * (1.f / DIM);
        float var = c * (1.f / DIM) - mean * mean;
        mv[0] = mean;
        mv[1] = rsqrtf(var + LNEPS);
    }
    __syncthreads();
    float mean = mv[0], rs = mv[1];
    int c0 = tid * 4;
    float4 gg = *(const float4*)(g + c0);
    float4 bb = *(const float4*)(b + c0);
    float4 o;
    o.x = (x.x - mean) * rs * gg.x + bb.x;
    o.y = (x.y - mean) * rs * gg.y + bb.y;
    o.z = (x.z - mean) * rs * gg.z + bb.z;
    o.w = (x.w - mean) * rs * gg.w + bb.w;
    *(float4*)(out + (size_t)s * DIM + c0) = o;
}

// ---------------- launch ----------------
extern "C" void kernel_launch(void* const* d_in, const int* in_sizes, int n_in,
                              void* d_out, int out_size) {
    const float* hs  = (const float*)d_in[0];
    const float* Wq  = (const float*)d_in[1];  const float* bq  = (const float*)d_in[2];
    const float* Wk  = (const float*)d_in[3];  const float* bk  = (const float*)d_in[4];
    const float* Wv  = (const float*)d_in[5];  const float* bv  = (const float*)d_in[6];
    const float* Wo  = (const float*)d_in[7];  const float* bo  = (const float*)d_in[8];
    const float* Weq = (const float*)d_in[9];  const float* beq = (const float*)d_in[10];
    const float* Wek = (const float*)d_in[11]; const float* bek = (const float*)d_in[12];
    const float* aw  = (const float*)d_in[13]; const float* ab  = (const float*)d_in[14];
    const float* pw  = (const float*)d_in[15]; const float* pb  = (const float*)d_in[16];
    const float* mw  = (const float*)d_in[17]; const float* mb  = (const float*)d_in[18];
    const float* lg  = (const float*)d_in[19]; const float* lb  = (const float*)d_in[20];
    float* out = (float*)d_out;

    static __nv_bfloat16* wb_p = nullptr;
    static __nv_bfloat16* ab_p = nullptr;
    if (!wb_p) {
        cudaGetSymbolAddress((void**)&wb_p, g_wb);
        cudaGetSymbolAddress((void**)&ab_p, g_ab);
        cudaFuncSetAttribute(k_attn_tc, cudaFuncAttributeMaxDynamicSharedMemorySize,
                             ATT_SMEM);
    }

    const int AN4 = SEQ * DIM / 4;     // 524288

    k_cvt1<<<(AN4 + 255) / 256, 256>>>(hs, ab_p, AN4);
    k_cvtw<<<dim3(1024, 6), 256>>>(Wq, Wk, Wv, Weq, Wek, Wo, wb_p);

    k_proj5<<<dim3(8, 16, 5), 256, GSMEM>>>(bq, bk, bv, beq, bek);
    k_ampph<<<2048, 256>>>(hs, aw, ab, pw, pb);
    k_mixed<<<dim3(64, 16), 256>>>(mw, mb);
    k_attn_tc<<<dim3(32, 16), 256, ATT_SMEM>>>();

    k_wo<<<dim3(8, 16), 256, GSMEM>>>(bo, hs);
    k_ln<<<2048, 256>>>(lg, lb, out);
}